// round 1
// baseline (speedup 1.0000x reference)
#include <cuda_runtime.h>

#define BHn 16
#define Ln  2048
#define DMn 256
#define VDn 512

// log2(0.9)
#define LOG2G (-0.15200309344504995f)

// Scratch (module-scope device arrays: allowed; no runtime allocation)
__device__ float g_q[(size_t)BHn * Ln * DMn];
__device__ float g_k[(size_t)BHn * Ln * DMn];
__device__ float g_v[(size_t)BHn * Ln * VDn];

// ---------------------------------------------------------------------------
// Projection GEMM: out[M=BH*L, N] = X[M, 256] @ W[256, N]
// MODE: 0 = plain (V), 1 = q rotary (+sin), 2 = k rotary (-sin)
// 128x128 tile, BK=8, 256 threads, 8x8 microtile.
// ---------------------------------------------------------------------------
template <int N, int MODE>
__global__ void __launch_bounds__(256) proj_kernel(const float* __restrict__ X,
                                                   const float* __restrict__ W) {
    __shared__ float As[8][128];
    __shared__ float Bs[8][128];
    const int t  = threadIdx.x;
    const int tx = t & 15, ty = t >> 4;
    const int mbase = blockIdx.y * 128;
    const int nbase = blockIdx.x * 128;
    const int arow = t >> 1,  acol = (t & 1) * 4;
    const int brow = t >> 5,  bcol = (t & 31) * 4;

    float acc[8][8];
#pragma unroll
    for (int i = 0; i < 8; i++)
#pragma unroll
        for (int j = 0; j < 8; j++) acc[i][j] = 0.f;

    const float* Aptr = X + (size_t)(mbase + arow) * DMn + acol;
    const float* Bptr = W + (size_t)brow * N + nbase + bcol;

    for (int k0 = 0; k0 < DMn; k0 += 8) {
        float4 av = *(const float4*)(Aptr + k0);
        float4 bv = *(const float4*)(Bptr + (size_t)k0 * N);
        __syncthreads();
        As[acol + 0][arow] = av.x;
        As[acol + 1][arow] = av.y;
        As[acol + 2][arow] = av.z;
        As[acol + 3][arow] = av.w;
        *(float4*)&Bs[brow][bcol] = bv;
        __syncthreads();
#pragma unroll
        for (int kk = 0; kk < 8; kk++) {
            float4 a0 = *(const float4*)&As[kk][ty * 4];
            float4 a1 = *(const float4*)&As[kk][64 + ty * 4];
            float4 b0 = *(const float4*)&Bs[kk][tx * 4];
            float4 b1 = *(const float4*)&Bs[kk][64 + tx * 4];
            float a[8] = {a0.x, a0.y, a0.z, a0.w, a1.x, a1.y, a1.z, a1.w};
            float b[8] = {b0.x, b0.y, b0.z, b0.w, b1.x, b1.y, b1.z, b1.w};
#pragma unroll
            for (int i = 0; i < 8; i++)
#pragma unroll
                for (int j = 0; j < 8; j++) acc[i][j] = fmaf(a[i], b[j], acc[i][j]);
        }
    }

    float* out = (MODE == 0) ? g_v : (MODE == 1 ? g_q : g_k);

#pragma unroll
    for (int i = 0; i < 8; i++) {
        const int rloc = (i < 4) ? (ty * 4 + i) : (64 + ty * 4 + (i - 4));
        const int grow = mbase + rloc;
        if (MODE != 0) {
            const int l = grow & (Ln - 1);
#pragma unroll
            for (int jh = 0; jh < 2; jh++) {
#pragma unroll
                for (int jp = 0; jp < 2; jp++) {
                    const int j   = jh * 4 + jp * 2;
                    const int col = nbase + jh * 64 + tx * 4 + jp * 2;
                    // theta_j = 10000^(-(col/2)/127)
                    float theta = exp2f(-(float)(col >> 1) * (13.287712379549449f / 127.0f));
                    float ang = (float)l * theta;
                    float sn, cs;
                    sincosf(ang, &sn, &cs);
                    float e = acc[i][j], o = acc[i][j + 1];
                    if (MODE == 1) {          // q: +sin
                        acc[i][j]     = e * cs - o * sn;
                        acc[i][j + 1] = o * cs + e * sn;
                    } else {                  // k: -sin
                        acc[i][j]     = e * cs + o * sn;
                        acc[i][j + 1] = o * cs - e * sn;
                    }
                }
            }
        }
        float4 v0 = make_float4(acc[i][0], acc[i][1], acc[i][2], acc[i][3]);
        float4 v1 = make_float4(acc[i][4], acc[i][5], acc[i][6], acc[i][7]);
        *(float4*)&out[(size_t)grow * N + nbase + tx * 4]      = v0;
        *(float4*)&out[(size_t)grow * N + nbase + 64 + tx * 4] = v1;
    }
}

// ---------------------------------------------------------------------------
// score[bh,l,m] = (q[l]·k[m]) / 16 * gamma^(l-m) / s_l   (causal, banded)
// Tiles with mb > lb or lb - mb > 8 are exactly zero (fp32 underflow of
// gamma^diff at diff >= 1025), matching the fp32 reference bit-for-bit.
// ---------------------------------------------------------------------------
__global__ void __launch_bounds__(256) score_kernel(float* __restrict__ score) {
    const int bh = blockIdx.z, lb = blockIdx.y, mb = blockIdx.x;
    const int lbase = lb * 128, mbase = mb * 128;
    float* out = score + (size_t)bh * Ln * Ln;
    const int t = threadIdx.x;

    if (mb > lb || lb - mb > 8) {
        const float4 z = make_float4(0.f, 0.f, 0.f, 0.f);
#pragma unroll
        for (int i = 0; i < 16; i++) {
            int idx = i * 256 + t;
            int r = idx >> 5, c4 = (idx & 31) * 4;
            *(float4*)&out[(size_t)(lbase + r) * Ln + mbase + c4] = z;
        }
        return;
    }

    const int tx = t & 15, ty = t >> 4;
    const int arow = t >> 1, acol = (t & 1) * 4;
    const float* A  = g_q + (size_t)bh * Ln * DMn + (size_t)(lbase + arow) * DMn + acol;
    const float* Bk = g_k + (size_t)bh * Ln * DMn + (size_t)(mbase + arow) * DMn + acol;

    __shared__ float As[8][128];
    __shared__ float Bs[8][128];
    float acc[8][8];
#pragma unroll
    for (int i = 0; i < 8; i++)
#pragma unroll
        for (int j = 0; j < 8; j++) acc[i][j] = 0.f;

    for (int k0 = 0; k0 < DMn; k0 += 8) {
        float4 av = *(const float4*)(A + k0);
        float4 bv = *(const float4*)(Bk + k0);
        __syncthreads();
        As[acol + 0][arow] = av.x;
        As[acol + 1][arow] = av.y;
        As[acol + 2][arow] = av.z;
        As[acol + 3][arow] = av.w;
        Bs[acol + 0][arow] = bv.x;
        Bs[acol + 1][arow] = bv.y;
        Bs[acol + 2][arow] = bv.z;
        Bs[acol + 3][arow] = bv.w;
        __syncthreads();
#pragma unroll
        for (int kk = 0; kk < 8; kk++) {
            float4 a0 = *(const float4*)&As[kk][ty * 4];
            float4 a1 = *(const float4*)&As[kk][64 + ty * 4];
            float4 b0 = *(const float4*)&Bs[kk][tx * 4];
            float4 b1 = *(const float4*)&Bs[kk][64 + tx * 4];
            float a[8] = {a0.x, a0.y, a0.z, a0.w, a1.x, a1.y, a1.z, a1.w};
            float b[8] = {b0.x, b0.y, b0.z, b0.w, b1.x, b1.y, b1.z, b1.w};
#pragma unroll
            for (int i = 0; i < 8; i++)
#pragma unroll
                for (int j = 0; j < 8; j++) acc[i][j] = fmaf(a[i], b[j], acc[i][j]);
        }
    }

#pragma unroll
    for (int i = 0; i < 8; i++) {
        const int rloc = (i < 4) ? (ty * 4 + i) : (64 + ty * 4 + (i - 4));
        const int l = lbase + rloc;
        // s_l = (1 - gamma^(l+1)) / (1 - gamma); D = gamma^diff / s_l (s_l >= 1)
        const float gpl   = exp2f((float)(l + 1) * LOG2G);
        const float scale = 0.0625f / ((1.0f - gpl) * 10.0f);
#pragma unroll
        for (int jh = 0; jh < 2; jh++) {
            float4 v;
            float* vp = &v.x;
#pragma unroll
            for (int jj = 0; jj < 4; jj++) {
                const int m = mbase + jh * 64 + tx * 4 + jj;
                float w = (m <= l) ? exp2f((float)(l - m) * LOG2G) * scale : 0.f;
                vp[jj] = acc[i][jh * 4 + jj] * w;
            }
            *(float4*)&out[(size_t)l * Ln + mbase + jh * 64 + tx * 4] = v;
        }
    }
}

// ---------------------------------------------------------------------------
// vt[bh,l,n] = sum_m score[bh,l,m] * v[bh,m,n], m restricted to the nonzero
// band (mb in [lb-8, lb]); everything outside is exactly zero in score.
// ---------------------------------------------------------------------------
__global__ void __launch_bounds__(256) vt_kernel(const float* __restrict__ score,
                                                 float* __restrict__ vt) {
    const int bh = blockIdx.z, lb = blockIdx.y, nb = blockIdx.x;
    const int lbase = lb * 128, nbase = nb * 128;
    const float* S = score + (size_t)bh * Ln * Ln;
    const float* V = g_v + (size_t)bh * Ln * VDn;
    const int t = threadIdx.x;
    const int tx = t & 15, ty = t >> 4;
    const int arow = t >> 1, acol = (t & 1) * 4;
    const int brow = t >> 5, bcol = (t & 31) * 4;

    __shared__ float As[8][128];
    __shared__ float Bs[8][128];
    float acc[8][8];
#pragma unroll
    for (int i = 0; i < 8; i++)
#pragma unroll
        for (int j = 0; j < 8; j++) acc[i][j] = 0.f;

    const int mb0 = (lb > 8) ? (lb - 8) : 0;
    const int kstart = mb0 * 128, kend = (lb + 1) * 128;

    const float* Ap = S + (size_t)(lbase + arow) * Ln + acol;
    const float* Bp = V + (size_t)brow * VDn + nbase + bcol;

    for (int k0 = kstart; k0 < kend; k0 += 8) {
        float4 av = *(const float4*)(Ap + k0);
        float4 bv = *(const float4*)(Bp + (size_t)k0 * VDn);
        __syncthreads();
        As[acol + 0][arow] = av.x;
        As[acol + 1][arow] = av.y;
        As[acol + 2][arow] = av.z;
        As[acol + 3][arow] = av.w;
        *(float4*)&Bs[brow][bcol] = bv;
        __syncthreads();
#pragma unroll
        for (int kk = 0; kk < 8; kk++) {
            float4 a0 = *(const float4*)&As[kk][ty * 4];
            float4 a1 = *(const float4*)&As[kk][64 + ty * 4];
            float4 b0 = *(const float4*)&Bs[kk][tx * 4];
            float4 b1 = *(const float4*)&Bs[kk][64 + tx * 4];
            float a[8] = {a0.x, a0.y, a0.z, a0.w, a1.x, a1.y, a1.z, a1.w};
            float b[8] = {b0.x, b0.y, b0.z, b0.w, b1.x, b1.y, b1.z, b1.w};
#pragma unroll
            for (int i = 0; i < 8; i++)
#pragma unroll
                for (int j = 0; j < 8; j++) acc[i][j] = fmaf(a[i], b[j], acc[i][j]);
        }
    }

#pragma unroll
    for (int i = 0; i < 8; i++) {
        const int rloc = (i < 4) ? (ty * 4 + i) : (64 + ty * 4 + (i - 4));
        const size_t row = (size_t)bh * Ln * VDn + (size_t)(lbase + rloc) * VDn;
        float4 v0 = make_float4(acc[i][0], acc[i][1], acc[i][2], acc[i][3]);
        float4 v1 = make_float4(acc[i][4], acc[i][5], acc[i][6], acc[i][7]);
        *(float4*)&vt[row + nbase + tx * 4]      = v0;
        *(float4*)&vt[row + nbase + 64 + tx * 4] = v1;
    }
}

// ---------------------------------------------------------------------------
extern "C" void kernel_launch(void* const* d_in, const int* in_sizes, int n_in,
                              void* d_out, int out_size) {
    const float* X  = (const float*)d_in[0];
    const float* WQ = (const float*)d_in[1];
    const float* WK = (const float*)d_in[2];
    const float* WV = (const float*)d_in[3];

    float* out       = (float*)d_out;
    float* out_vt    = out;                               // [BH, L, VD]
    float* out_score = out + (size_t)BHn * Ln * VDn;      // [BH, L, L]

    dim3 blk(256);
    proj_kernel<DMn, 1><<<dim3(DMn / 128, (BHn * Ln) / 128), blk>>>(X, WQ);
    proj_kernel<DMn, 2><<<dim3(DMn / 128, (BHn * Ln) / 128), blk>>>(X, WK);
    proj_kernel<VDn, 0><<<dim3(VDn / 128, (BHn * Ln) / 128), blk>>>(X, WV);
    score_kernel<<<dim3(Ln / 128, Ln / 128, BHn), blk>>>(out_score);
    vt_kernel<<<dim3(VDn / 128, Ln / 128, BHn), blk>>>(out_score, out_vt);
}

// round 3
// speedup vs baseline: 1.5628x; 1.5628x over previous
#include <cuda_runtime.h>
#include <cstdint>

#define BH  16
#define LN  2048
#define DMn 256
#define VDn 512
#define LOG2G (-0.15200309344504995f)

// tcgen05 only exists in the arch-specific (sm_103a/sm_100a) device pass.
// The harness also compiles a plain compute_103 pass where these instructions
// are illegal, so guard them and provide a correct SIMT fallback there.
#if defined(__CUDA_ARCH_FEAT_SM103_ALL) || defined(__CUDA_ARCH_FEAT_SM100_ALL) || \
    (defined(__CUDA_ARCH_SPECIFIC__) && (__CUDA_ARCH_SPECIFIC__ >= 1000))
#define TC_OK 1
#else
#define TC_OK 0
#endif

// device scratch (no runtime allocation)
__device__ float g_q [(size_t)BH * LN * DMn];
__device__ float g_k [(size_t)BH * LN * DMn];
__device__ float g_vt[(size_t)BH * VDn * LN];   // v transposed: [bh][n][m]

#define NBUF 3
#define STAGE_BYTES 65536              // Ahi,Alo,Bhi,Blo @ 16KB each
#define SMEM_BUF0   1024
#define SMEM_TOTAL  (SMEM_BUF0 + NBUF * STAGE_BYTES)   // 197632 B

static __device__ __forceinline__ uint32_t s2u(const void* p) {
    uint32_t a;
    asm("{ .reg .u64 t; cvta.to.shared.u64 t, %1; cvt.u32.u64 %0, t; }"
        : "=r"(a) : "l"(p));
    return a;
}
static __device__ __forceinline__ float tf32r(float x) {
    uint32_t u;
    asm("cvt.rna.tf32.f32 %0, %1;" : "=r"(u) : "f"(x));
    return __uint_as_float(u);
}

#if TC_OK
// K-major SW128 descriptor: layout=SW128, version=1(Blackwell), SBO=64, LBO=1
static __device__ __forceinline__ uint64_t mkdesc(uint32_t addr) {
    const uint64_t base = (2ull << 61) | (1ull << 46) | (64ull << 32) | (1ull << 16);
    return base | ((uint64_t)(addr >> 4) & 0x3FFF);
}
static __device__ __forceinline__ void mma_tf32(uint32_t d, uint64_t a, uint64_t b,
                                                uint32_t idesc, uint32_t en) {
    asm volatile(
        "{\n\t.reg .pred p;\n\tsetp.ne.u32 p, %4, 0;\n\t"
        "tcgen05.mma.cta_group::1.kind::tf32 [%0], %1, %2, %3, p;\n\t}"
        :: "r"(d), "l"(a), "l"(b), "r"(idesc), "r"(en) : "memory");
}
#define TC_ALLOC(sm, n)  asm volatile("tcgen05.alloc.cta_group::1.sync.aligned.shared::cta.b32 [%0], %1;" :: "r"(sm), "r"(n) : "memory")
#define TC_DEALLOC(t, n) asm volatile("tcgen05.dealloc.cta_group::1.sync.aligned.b32 %0, %1;" :: "r"(t), "r"(n))
#define TC_RELINQ()      asm volatile("tcgen05.relinquish_alloc_permit.cta_group::1.sync.aligned;")
#define TC_COMMIT(mb)    asm volatile("tcgen05.commit.cta_group::1.mbarrier::arrive::one.shared::cluster.b64 [%0];" :: "r"(mb) : "memory")
#define TC_FENCE_AFTER() asm volatile("tcgen05.fence::after_thread_sync;" ::: "memory")
#define TC_WAIT_LD()     asm volatile("tcgen05.wait::ld.sync.aligned;" ::: "memory")
#define FENCE_ASYNC()    asm volatile("fence.proxy.async.shared::cta;" ::: "memory")
#define MBAR_INIT(mb, c) asm volatile("mbarrier.init.shared.b64 [%0], %1;" :: "r"(mb), "r"(c) : "memory")

#define MBAR_WAIT(mb, ph) do {                                                   \
    uint32_t _m = (mb), _p = (ph), _d;                                           \
    asm volatile("{\n\t.reg .pred p;\n\t"                                        \
        "mbarrier.try_wait.parity.acquire.cta.shared::cta.b64 p, [%1], %2;\n\t"  \
        "selp.b32 %0, 1, 0, p;\n\t}"                                             \
        : "=r"(_d) : "r"(_m), "r"(_p) : "memory");                               \
    if (!_d) {                                                                   \
        asm volatile("{\n\t.reg .pred P1;\n\t"                                   \
            "W_%=:\n\t"                                                          \
            "mbarrier.try_wait.parity.acquire.cta.shared::cta.b64 P1, [%0], %1, 0x989680;\n\t" \
            "@P1 bra.uni D_%=;\n\tbra.uni W_%=;\n\tD_%=:\n\t}"                   \
            :: "r"(_m), "r"(_p) : "memory");                                     \
    }                                                                            \
} while (0)

#define TC_LD_X32(r, ta)                                                         \
    asm volatile("tcgen05.ld.sync.aligned.32x32b.x32.b32 "                       \
        "{%0,%1,%2,%3,%4,%5,%6,%7,%8,%9,%10,%11,%12,%13,%14,%15,"                \
        "%16,%17,%18,%19,%20,%21,%22,%23,%24,%25,%26,%27,%28,%29,%30,%31}, [%32];" \
        : "=r"((r)[0]),"=r"((r)[1]),"=r"((r)[2]),"=r"((r)[3]),                   \
          "=r"((r)[4]),"=r"((r)[5]),"=r"((r)[6]),"=r"((r)[7]),                   \
          "=r"((r)[8]),"=r"((r)[9]),"=r"((r)[10]),"=r"((r)[11]),                 \
          "=r"((r)[12]),"=r"((r)[13]),"=r"((r)[14]),"=r"((r)[15]),               \
          "=r"((r)[16]),"=r"((r)[17]),"=r"((r)[18]),"=r"((r)[19]),               \
          "=r"((r)[20]),"=r"((r)[21]),"=r"((r)[22]),"=r"((r)[23]),               \
          "=r"((r)[24]),"=r"((r)[25]),"=r"((r)[26]),"=r"((r)[27]),               \
          "=r"((r)[28]),"=r"((r)[29]),"=r"((r)[30]),"=r"((r)[31])                \
        : "r"(ta))

// idesc: dtype F32 (1<<4), atype TF32 (2<<7), btype TF32 (2<<10),
//        N=128 ((128/8)<<17), M=128 ((128/16)<<24)
#define IDESC_TF32 0x08200910u
#endif  // TC_OK

// MODE: 0=proj Q (+sin rotary), 1=proj K (-sin), 2=proj V (write v^T),
//       3=score (decay epilogue), 4=vt
template <int MODE>
__global__ void __launch_bounds__(256, 1)
gemm_kernel(const float* __restrict__ X, const float* __restrict__ W,
            float* __restrict__ score, float* __restrict__ vt) {
    extern __shared__ char smem[];
    const int tid = threadIdx.x;

    // --- tile coordinates & operand sources (common to both paths) --------
    int nbase = 0, mtile = 0, bh = 0, lb = 0, mb = 0;
    int k_begin = 0, S = 8, Wn = 0;
    const float* Asrc = nullptr;
    const float* Bsrc = nullptr;
    size_t lda = 0, ldb = 0;

    if constexpr (MODE <= 2) {
        nbase = blockIdx.x * 128;
        mtile = blockIdx.y;
        Asrc  = X + (size_t)mtile * 128 * DMn;  lda = DMn;
        Wn    = (MODE == 2) ? VDn : DMn;
        (void)Wn;
    } else if constexpr (MODE == 3) {
        bh = blockIdx.z; lb = blockIdx.y;
        mb = lb - (int)blockIdx.x;
        if (mb < 0) return;
        Asrc = g_q + ((size_t)bh * LN + (size_t)lb * 128) * DMn;  lda = DMn;
        Bsrc = g_k + ((size_t)bh * LN + (size_t)mb * 128) * DMn;  ldb = DMn;
    } else {
        bh = blockIdx.z; lb = blockIdx.y; nbase = blockIdx.x * 128;
        const int mb0 = (lb > 8) ? lb - 8 : 0;
        k_begin = mb0 * 128;
        S = ((lb + 1) * 128 - k_begin) / 32;
        Asrc = score + ((size_t)bh * LN + (size_t)lb * 128) * LN;  lda = LN;
        Bsrc = g_vt + (size_t)bh * VDn * LN + (size_t)nbase * LN;  ldb = LN;
    }

#if TC_OK
    // =============================== tcgen05 path =========================
    const uint32_t smem_base = s2u(smem);
    const int wid = tid >> 5, lane = tid & 31;

    if (wid == 0) TC_ALLOC(smem_base, 128);
    if (tid == 0) {
        MBAR_INIT(smem_base + 16, 1);
        MBAR_INIT(smem_base + 24, 1);
        MBAR_INIT(smem_base + 32, 1);
    }
    __syncthreads();
    uint32_t tmem;
    asm volatile("ld.shared.b32 %0, [%1];" : "=r"(tmem) : "r"(smem_base));

    int ph0 = 0, ph1 = 0, ph2 = 0;
    for (int s = 0; s < S; s++) {
        const int b = s % NBUF;
        if (s >= NBUF) {
            if (b == 0)      { MBAR_WAIT(smem_base + 16, ph0); ph0 ^= 1; }
            else if (b == 1) { MBAR_WAIT(smem_base + 24, ph1); ph1 ^= 1; }
            else             { MBAR_WAIT(smem_base + 32, ph2); ph2 ^= 1; }
        }
        const int k0 = k_begin + s * 32;
        char* sb = smem + SMEM_BUF0 + b * STAGE_BYTES;

        {   // A tile: 128 rows x 32 f32, K-major, SW128, hi/lo split
            const float* src = Asrc + k0;
#pragma unroll
            for (int i = 0; i < 4; i++) {
                const int idx = i * 256 + tid;
                const int row = idx >> 3, c4 = (idx & 7) * 4;
                float4 v = *(const float4*)(src + (size_t)row * lda + c4);
                float4 h, l;
                h.x = tf32r(v.x); l.x = tf32r(v.x - h.x);
                h.y = tf32r(v.y); l.y = tf32r(v.y - h.y);
                h.z = tf32r(v.z); l.z = tf32r(v.z - h.z);
                h.w = tf32r(v.w); l.w = tf32r(v.w - h.w);
                uint32_t byte = row * 128 + c4 * 4;
                uint32_t sw = byte ^ ((byte >> 3) & 0x70);
                *(float4*)(sb + sw)         = h;
                *(float4*)(sb + 16384 + sw) = l;
            }
        }
        if constexpr (MODE <= 2) {
            // B[n][k] = W[k][n]: transpose-on-load
            const int WN = (MODE == 2) ? VDn : DMn;
            const float* src = W + (size_t)k0 * WN + nbase;
#pragma unroll
            for (int i = 0; i < 4; i++) {
                const int idx = i * 256 + tid;
                const int k = idx >> 5, n4 = (idx & 31) * 4;
                float4 v = *(const float4*)(src + (size_t)k * WN + n4);
                const float* vp = &v.x;
#pragma unroll
                for (int j = 0; j < 4; j++) {
                    float x = vp[j];
                    float h = tf32r(x), l = tf32r(x - h);
                    uint32_t byte = (n4 + j) * 128 + k * 4;
                    uint32_t sw = byte ^ ((byte >> 3) & 0x70);
                    *(float*)(sb + 32768 + sw) = h;
                    *(float*)(sb + 49152 + sw) = l;
                }
            }
        } else {
            const float* src = Bsrc + k0;
#pragma unroll
            for (int i = 0; i < 4; i++) {
                const int idx = i * 256 + tid;
                const int row = idx >> 3, c4 = (idx & 7) * 4;
                float4 v = *(const float4*)(src + (size_t)row * ldb + c4);
                float4 h, l;
                h.x = tf32r(v.x); l.x = tf32r(v.x - h.x);
                h.y = tf32r(v.y); l.y = tf32r(v.y - h.y);
                h.z = tf32r(v.z); l.z = tf32r(v.z - h.z);
                h.w = tf32r(v.w); l.w = tf32r(v.w - h.w);
                uint32_t byte = row * 128 + c4 * 4;
                uint32_t sw = byte ^ ((byte >> 3) & 0x70);
                *(float4*)(sb + 32768 + sw) = h;
                *(float4*)(sb + 49152 + sw) = l;
            }
        }
        __syncthreads();

        if (tid == 0) {
            FENCE_ASYNC();
            const uint32_t base = smem_base + SMEM_BUF0 + b * STAGE_BYTES;
            const uint64_t ah  = mkdesc(base);
            const uint64_t al  = mkdesc(base + 16384);
            const uint64_t bh_ = mkdesc(base + 32768);
            const uint64_t bl  = mkdesc(base + 49152);
#pragma unroll
            for (int ks = 0; ks < 4; ks++) {
                mma_tf32(tmem, ah + ks * 2, bh_ + ks * 2, IDESC_TF32,
                         (s > 0 || ks > 0) ? 1u : 0u);
                mma_tf32(tmem, ah + ks * 2, bl + ks * 2, IDESC_TF32, 1u);
                mma_tf32(tmem, al + ks * 2, bh_ + ks * 2, IDESC_TF32, 1u);
            }
            TC_COMMIT(smem_base + 16 + b * 8);
        }
    }
    {   // final wait (commit covers all previously issued MMAs)
        const int b = (S - 1) % NBUF;
        if (b == 0)      MBAR_WAIT(smem_base + 16, ph0);
        else if (b == 1) MBAR_WAIT(smem_base + 24, ph1);
        else             MBAR_WAIT(smem_base + 32, ph2);
    }
    TC_FENCE_AFTER();
    __syncthreads();

    float* tsm = (float*)(smem + SMEM_BUF0);   // 128 x (pitch 36)
#pragma unroll 1
    for (int ch = 0; ch < 4; ch++) {
        if (wid < 4) {
            uint32_t r[32];
            TC_LD_X32(r, tmem + ch * 32);
            TC_WAIT_LD();
            const int row = wid * 32 + lane;

            if constexpr (MODE == 0 || MODE == 1) {
                const int l = (mtile * 128 + row) & (LN - 1);
#pragma unroll
                for (int c = 0; c < 32; c += 2) {
                    const int col = nbase + ch * 32 + c;
                    float theta = exp2f(-(float)(col >> 1) *
                                        (13.287712379549449f / 127.0f));
                    float sn, cs;
                    sincosf((float)l * theta, &sn, &cs);
                    float e = __uint_as_float(r[c]);
                    float o = __uint_as_float(r[c + 1]);
                    float ne, no;
                    if (MODE == 0) { ne = e * cs - o * sn; no = o * cs + e * sn; }
                    else           { ne = e * cs + o * sn; no = o * cs - e * sn; }
                    r[c]     = __float_as_uint(ne);
                    r[c + 1] = __float_as_uint(no);
                }
            } else if constexpr (MODE == 3) {
                const int l = lb * 128 + row;
                const float gpl = exp2f((float)(l + 1) * LOG2G);
                const float scale = 0.0625f / ((1.0f - gpl) * 10.0f);
#pragma unroll
                for (int c = 0; c < 32; c++) {
                    const int m = mb * 128 + ch * 32 + c;
                    float w = (m <= l) ? exp2f((float)(l - m) * LOG2G) * scale : 0.f;
                    r[c] = __float_as_uint(__uint_as_float(r[c]) * w);
                }
            }

            if constexpr (MODE == 2) {
                const int mrow = mtile * 128 + row;
                const int bhv = mrow >> 11, lloc = mrow & (LN - 1);
                float* dst = g_vt + (size_t)bhv * VDn * LN + lloc;
#pragma unroll
                for (int c = 0; c < 32; c++)
                    dst[(size_t)(nbase + ch * 32 + c) * LN] = __uint_as_float(r[c]);
            } else {
                float* d0 = tsm + row * 36;
#pragma unroll
                for (int c4 = 0; c4 < 32; c4 += 4)
                    *(float4*)(d0 + c4) = make_float4(
                        __uint_as_float(r[c4]), __uint_as_float(r[c4 + 1]),
                        __uint_as_float(r[c4 + 2]), __uint_as_float(r[c4 + 3]));
            }
        }
        __syncthreads();
        if constexpr (MODE != 2) {
            float* outp; size_t ldo; int cbase;
            if constexpr (MODE <= 1) {
                outp = (MODE == 0 ? g_q : g_k) + (size_t)mtile * 128 * DMn;
                ldo = DMn; cbase = nbase + ch * 32;
            } else if constexpr (MODE == 3) {
                outp = score + ((size_t)bh * LN + (size_t)lb * 128) * LN;
                ldo = LN; cbase = mb * 128 + ch * 32;
            } else {
                outp = vt + ((size_t)bh * LN + (size_t)lb * 128) * VDn;
                ldo = VDn; cbase = nbase + ch * 32;
            }
#pragma unroll
            for (int i = 0; i < 4; i++) {
                const int idx = i * 256 + tid;
                const int rw = idx >> 3, c4 = (idx & 7) * 4;
                float4 v = *(const float4*)(tsm + rw * 36 + c4);
                *(float4*)(outp + (size_t)rw * ldo + cbase + c4) = v;
            }
        }
        __syncthreads();
    }

    if (wid == 0) {
        TC_RELINQ();
        TC_DEALLOC(tmem, 128);
    }

#else
    // ========================= SIMT fallback path ==========================
    // Correct (slower) implementation for non-arch-specific device passes.
    float* As = (float*)smem;            // [8][128] k-major
    float* Bs = As + 8 * 128;            // [8][128] (k, n)
    const int tx = tid & 15, ty = tid >> 4;
    const int arow = tid >> 1, acol = (tid & 1) * 4;
    const int brow = tid >> 5, bcol = (tid & 31) * 4;

    float acc[8][8];
#pragma unroll
    for (int i = 0; i < 8; i++)
#pragma unroll
        for (int j = 0; j < 8; j++) acc[i][j] = 0.f;

    const int k_end = k_begin + S * 32;
    for (int k0 = k_begin; k0 < k_end; k0 += 8) {
        float4 av = *(const float4*)(Asrc + (size_t)arow * lda + k0 + acol);
        float4 bv;
        if constexpr (MODE <= 2) {
            const int WN = (MODE == 2) ? VDn : DMn;
            bv = *(const float4*)(W + (size_t)(k0 + brow) * WN + nbase + bcol);
        } else if constexpr (MODE == 3) {
            bv = *(const float4*)(Bsrc + (size_t)arow * ldb + k0 + acol);
        } else {
            const int n = tid & 127, kq = tid >> 7;
            bv = *(const float4*)(Bsrc + (size_t)n * LN + k0 + kq * 4);
        }
        __syncthreads();
        As[(acol + 0) * 128 + arow] = av.x;
        As[(acol + 1) * 128 + arow] = av.y;
        As[(acol + 2) * 128 + arow] = av.z;
        As[(acol + 3) * 128 + arow] = av.w;
        if constexpr (MODE <= 2) {
            *(float4*)&Bs[brow * 128 + bcol] = bv;
        } else if constexpr (MODE == 3) {
            Bs[(acol + 0) * 128 + arow] = bv.x;
            Bs[(acol + 1) * 128 + arow] = bv.y;
            Bs[(acol + 2) * 128 + arow] = bv.z;
            Bs[(acol + 3) * 128 + arow] = bv.w;
        } else {
            const int n = tid & 127, kq = tid >> 7;
            Bs[(kq * 4 + 0) * 128 + n] = bv.x;
            Bs[(kq * 4 + 1) * 128 + n] = bv.y;
            Bs[(kq * 4 + 2) * 128 + n] = bv.z;
            Bs[(kq * 4 + 3) * 128 + n] = bv.w;
        }
        __syncthreads();
#pragma unroll
        for (int kk = 0; kk < 8; kk++) {
            float4 a0 = *(const float4*)&As[kk * 128 + ty * 4];
            float4 a1 = *(const float4*)&As[kk * 128 + 64 + ty * 4];
            float4 b0 = *(const float4*)&Bs[kk * 128 + tx * 4];
            float4 b1 = *(const float4*)&Bs[kk * 128 + 64 + tx * 4];
            float a[8] = {a0.x, a0.y, a0.z, a0.w, a1.x, a1.y, a1.z, a1.w};
            float bb[8] = {b0.x, b0.y, b0.z, b0.w, b1.x, b1.y, b1.z, b1.w};
#pragma unroll
            for (int i = 0; i < 8; i++)
#pragma unroll
                for (int j = 0; j < 8; j++) acc[i][j] = fmaf(a[i], bb[j], acc[i][j]);
        }
    }

#pragma unroll
    for (int i = 0; i < 8; i++) {
        const int rloc = (i < 4) ? (ty * 4 + i) : (64 + ty * 4 + (i - 4));
        if constexpr (MODE == 0 || MODE == 1) {
            const int grow = mtile * 128 + rloc;
            const int l = grow & (LN - 1);
            float* outp = (MODE == 0 ? g_q : g_k);
#pragma unroll
            for (int j = 0; j < 8; j += 2) {
                const int col = (j < 4) ? (nbase + tx * 4 + j)
                                        : (nbase + 64 + tx * 4 + (j - 4));
                float theta = exp2f(-(float)(col >> 1) *
                                    (13.287712379549449f / 127.0f));
                float sn, cs;
                sincosf((float)l * theta, &sn, &cs);
                float e = acc[i][j], o = acc[i][j + 1];
                float ne, no;
                if (MODE == 0) { ne = e * cs - o * sn; no = o * cs + e * sn; }
                else           { ne = e * cs + o * sn; no = o * cs - e * sn; }
                outp[(size_t)grow * DMn + col]     = ne;
                outp[(size_t)grow * DMn + col + 1] = no;
            }
        } else if constexpr (MODE == 2) {
            const int grow = mtile * 128 + rloc;
            const int bhv = grow >> 11, lloc = grow & (LN - 1);
#pragma unroll
            for (int j = 0; j < 8; j++) {
                const int col = (j < 4) ? (nbase + tx * 4 + j)
                                        : (nbase + 64 + tx * 4 + (j - 4));
                g_vt[(size_t)bhv * VDn * LN + (size_t)col * LN + lloc] = acc[i][j];
            }
        } else if constexpr (MODE == 3) {
            const int l = lb * 128 + rloc;
            const float gpl = exp2f((float)(l + 1) * LOG2G);
            const float scale = 0.0625f / ((1.0f - gpl) * 10.0f);
            float* outp = score + ((size_t)bh * LN + (size_t)l) * LN;
#pragma unroll
            for (int j = 0; j < 8; j++) {
                const int m = mb * 128 + ((j < 4) ? (tx * 4 + j)
                                                  : (64 + tx * 4 + (j - 4)));
                float w = (m <= l) ? exp2f((float)(l - m) * LOG2G) * scale : 0.f;
                outp[m] = acc[i][j] * w;
            }
        } else {
            float* outp = vt + ((size_t)bh * LN + (size_t)(lb * 128 + rloc)) * VDn;
#pragma unroll
            for (int j = 0; j < 8; j++) {
                const int col = (j < 4) ? (nbase + tx * 4 + j)
                                        : (nbase + 64 + tx * 4 + (j - 4));
                outp[col] = acc[i][j];
            }
        }
    }
#endif  // TC_OK
}

// zero-fill score tiles outside the decay band (exact fp32 underflow zeros)
__global__ void __launch_bounds__(256) score_zero(float* __restrict__ score) {
    const int bhq = blockIdx.z, lbq = blockIdx.y, mbq = blockIdx.x;
    const int d = lbq - mbq;
    if (d >= 0 && d <= 8) return;
    float* outp = score + ((size_t)bhq * LN + (size_t)lbq * 128) * LN + mbq * 128;
    const float4 z = make_float4(0.f, 0.f, 0.f, 0.f);
    const int tid = threadIdx.x;
#pragma unroll
    for (int i = 0; i < 16; i++) {
        const int idx = i * 256 + tid;
        const int r = idx >> 5, c4 = (idx & 31) * 4;
        *(float4*)(outp + (size_t)r * LN + c4) = z;
    }
}

// ---------------------------------------------------------------------------
extern "C" void kernel_launch(void* const* d_in, const int* in_sizes, int n_in,
                              void* d_out, int out_size) {
    const float* X  = (const float*)d_in[0];
    const float* WQ = (const float*)d_in[1];
    const float* WK = (const float*)d_in[2];
    const float* WV = (const float*)d_in[3];

    float* out       = (float*)d_out;
    float* out_vt    = out;                           // [BH, L, VD]
    float* out_score = out + (size_t)BH * LN * VDn;   // [BH, L, L]

    static bool attr_done = false;
    if (!attr_done) {
        cudaFuncSetAttribute(gemm_kernel<0>, cudaFuncAttributeMaxDynamicSharedMemorySize, SMEM_TOTAL);
        cudaFuncSetAttribute(gemm_kernel<1>, cudaFuncAttributeMaxDynamicSharedMemorySize, SMEM_TOTAL);
        cudaFuncSetAttribute(gemm_kernel<2>, cudaFuncAttributeMaxDynamicSharedMemorySize, SMEM_TOTAL);
        cudaFuncSetAttribute(gemm_kernel<3>, cudaFuncAttributeMaxDynamicSharedMemorySize, SMEM_TOTAL);
        cudaFuncSetAttribute(gemm_kernel<4>, cudaFuncAttributeMaxDynamicSharedMemorySize, SMEM_TOTAL);
        attr_done = true;
    }

    gemm_kernel<0><<<dim3(2, 256), 256, SMEM_TOTAL>>>(X, WQ, nullptr, nullptr);
    gemm_kernel<1><<<dim3(2, 256), 256, SMEM_TOTAL>>>(X, WK, nullptr, nullptr);
    gemm_kernel<2><<<dim3(4, 256), 256, SMEM_TOTAL>>>(X, WV, nullptr, nullptr);
    score_zero<<<dim3(16, 16, 16), 256>>>(out_score);
    gemm_kernel<3><<<dim3(9, 16, 16), 256, SMEM_TOTAL>>>(nullptr, nullptr, out_score, nullptr);
    gemm_kernel<4><<<dim3(4, 16, 16), 256, SMEM_TOTAL>>>(nullptr, nullptr, out_score, out_vt);
}

// round 4
// speedup vs baseline: 3.5775x; 2.2892x over previous
#include <cuda_runtime.h>
#include <cuda_bf16.h>
#include <cuda.h>
#include <cstdint>

#define BHc 16
#define LNc 2048
#define DMc 256
#define VDc 512
#define LOG2G (-0.15200309344504995f)

#if defined(__CUDA_ARCH_FEAT_SM103_ALL) || defined(__CUDA_ARCH_FEAT_SM100_ALL) || \
    (defined(__CUDA_ARCH_SPECIFIC__) && (__CUDA_ARCH_SPECIFIC__ >= 1000))
#define TC_OK 1
#else
#define TC_OK 0
#endif

// ---------------- scratch (bf16 hi/lo split pairs) -------------------------
__device__ __align__(1024) __nv_bfloat16 g_x_hi [32768u * 256];
__device__ __align__(1024) __nv_bfloat16 g_x_lo [32768u * 256];
__device__ __align__(1024) __nv_bfloat16 g_w_hi [1024u  * 256];   // [n:1024][k:256] (Q|K|V)
__device__ __align__(1024) __nv_bfloat16 g_w_lo [1024u  * 256];
__device__ __align__(1024) __nv_bfloat16 g_q_hi [32768u * 256];
__device__ __align__(1024) __nv_bfloat16 g_q_lo [32768u * 256];
__device__ __align__(1024) __nv_bfloat16 g_k_hi [32768u * 256];
__device__ __align__(1024) __nv_bfloat16 g_k_lo [32768u * 256];
__device__ __align__(1024) __nv_bfloat16 g_vt_hi[8192u  * 2048];  // [bh*512+n][m]
__device__ __align__(1024) __nv_bfloat16 g_vt_lo[8192u  * 2048];
__device__ __align__(1024) __nv_bfloat16 g_s_hi [(size_t)294912 * 128]; // [tile*128+l][m]
__device__ __align__(1024) __nv_bfloat16 g_s_lo [(size_t)294912 * 128];

#define NBUF 3
#define STAGE_BYTES 65536          // a_hi,a_lo,b_hi,b_lo @ 16KB each
#define SMEM_BUF0   1024
#define SMEM_TOTAL  (SMEM_BUF0 + NBUF * STAGE_BYTES)

// ---------------- small helpers --------------------------------------------
static __device__ __forceinline__ uint32_t s2u(const void* p) {
    uint32_t a;
    asm("{ .reg .u64 t; cvta.to.shared.u64 t, %1; cvt.u32.u64 %0, t; }"
        : "=r"(a) : "l"(p));
    return a;
}
// pack two f32 into bf16x2 hi + bf16x2 lo (x = hi + lo)
static __device__ __forceinline__ void split2(float x0, float x1,
                                              uint32_t& h, uint32_t& l) {
    asm("cvt.rn.bf16x2.f32 %0, %1, %2;" : "=r"(h) : "f"(x1), "f"(x0));
    float h0 = __uint_as_float(h << 16);
    float h1 = __uint_as_float(h & 0xffff0000u);
    asm("cvt.rn.bf16x2.f32 %0, %1, %2;" : "=r"(l) : "f"(x1 - h1), "f"(x0 - h0));
}
static __device__ __forceinline__ void split1(float x, __nv_bfloat16& h,
                                              __nv_bfloat16& l) {
    h = __float2bfloat16_rn(x);
    l = __float2bfloat16_rn(x - __bfloat162float(h));
}
static __device__ __forceinline__ float joinf(const __nv_bfloat16* hi,
                                              const __nv_bfloat16* lo, size_t i) {
    return __bfloat162float(hi[i]) + __bfloat162float(lo[i]);
}

#if TC_OK
static __device__ __forceinline__ uint64_t mkdesc(uint32_t addr) {
    const uint64_t base = (2ull << 61) | (1ull << 46) | (64ull << 32) | (1ull << 16);
    return base | ((uint64_t)(addr >> 4) & 0x3FFF);
}
static __device__ __forceinline__ void mma_bf16(uint32_t d, uint64_t a, uint64_t b,
                                                uint32_t idesc, uint32_t en) {
    asm volatile(
        "{\n\t.reg .pred p;\n\tsetp.ne.u32 p, %4, 0;\n\t"
        "tcgen05.mma.cta_group::1.kind::f16 [%0], %1, %2, %3, p;\n\t}"
        :: "r"(d), "l"(a), "l"(b), "r"(idesc), "r"(en) : "memory");
}
static __device__ __forceinline__ void tma2d(uint32_t dst, const CUtensorMap* m,
                                             int x, int y, uint32_t mbar) {
    asm volatile(
        "cp.async.bulk.tensor.2d.shared::cta.global.tile.mbarrier::complete_tx::bytes "
        "[%0], [%1, {%2, %3}], [%4];"
        :: "r"(dst), "l"((const void*)m), "r"(x), "r"(y), "r"(mbar) : "memory");
}
#define TC_ALLOC(sm, n)  asm volatile("tcgen05.alloc.cta_group::1.sync.aligned.shared::cta.b32 [%0], %1;" :: "r"(sm), "r"(n) : "memory")
#define TC_DEALLOC(t, n) asm volatile("tcgen05.dealloc.cta_group::1.sync.aligned.b32 %0, %1;" :: "r"(t), "r"(n))
#define TC_RELINQ()      asm volatile("tcgen05.relinquish_alloc_permit.cta_group::1.sync.aligned;")
#define TC_COMMIT(mb)    asm volatile("tcgen05.commit.cta_group::1.mbarrier::arrive::one.shared::cluster.b64 [%0];" :: "r"(mb) : "memory")
#define TC_FENCE_AFTER() asm volatile("tcgen05.fence::after_thread_sync;" ::: "memory")
#define TC_WAIT_LD()     asm volatile("tcgen05.wait::ld.sync.aligned;" ::: "memory")
#define MBAR_INIT(mb, c) asm volatile("mbarrier.init.shared.b64 [%0], %1;" :: "r"(mb), "r"(c) : "memory")
#define EXPECT_TX(mb, n) asm volatile("mbarrier.arrive.expect_tx.shared.b64 _, [%0], %1;" :: "r"(mb), "r"(n) : "memory")

#define MBAR_WAIT(mb, ph) do {                                                   \
    uint32_t _m = (mb), _p = (ph), _d;                                           \
    asm volatile("{\n\t.reg .pred p;\n\t"                                        \
        "mbarrier.try_wait.parity.acquire.cta.shared::cta.b64 p, [%1], %2;\n\t"  \
        "selp.b32 %0, 1, 0, p;\n\t}"                                             \
        : "=r"(_d) : "r"(_m), "r"(_p) : "memory");                               \
    if (!_d) {                                                                   \
        asm volatile("{\n\t.reg .pred P1;\n\t"                                   \
            "W_%=:\n\t"                                                          \
            "mbarrier.try_wait.parity.acquire.cta.shared::cta.b64 P1, [%0], %1, 0x989680;\n\t" \
            "@P1 bra.uni D_%=;\n\tbra.uni W_%=;\n\tD_%=:\n\t}"                   \
            :: "r"(_m), "r"(_p) : "memory");                                     \
    }                                                                            \
} while (0)

#define TC_LD_X32(r, ta)                                                         \
    asm volatile("tcgen05.ld.sync.aligned.32x32b.x32.b32 "                       \
        "{%0,%1,%2,%3,%4,%5,%6,%7,%8,%9,%10,%11,%12,%13,%14,%15,"                \
        "%16,%17,%18,%19,%20,%21,%22,%23,%24,%25,%26,%27,%28,%29,%30,%31}, [%32];" \
        : "=r"((r)[0]),"=r"((r)[1]),"=r"((r)[2]),"=r"((r)[3]),                   \
          "=r"((r)[4]),"=r"((r)[5]),"=r"((r)[6]),"=r"((r)[7]),                   \
          "=r"((r)[8]),"=r"((r)[9]),"=r"((r)[10]),"=r"((r)[11]),                 \
          "=r"((r)[12]),"=r"((r)[13]),"=r"((r)[14]),"=r"((r)[15]),               \
          "=r"((r)[16]),"=r"((r)[17]),"=r"((r)[18]),"=r"((r)[19]),               \
          "=r"((r)[20]),"=r"((r)[21]),"=r"((r)[22]),"=r"((r)[23]),               \
          "=r"((r)[24]),"=r"((r)[25]),"=r"((r)[26]),"=r"((r)[27]),               \
          "=r"((r)[28]),"=r"((r)[29]),"=r"((r)[30]),"=r"((r)[31])                \
        : "r"(ta))

// bf16 MMA idesc: dtype F32, a/b BF16, N=128, M=128
#define IDESC_BF16 0x08200490u
#endif

// ---------------- prep kernels ---------------------------------------------
__global__ void __launch_bounds__(256) split_x_k(const float* __restrict__ X) {
    size_t i = ((size_t)blockIdx.x * 256 + threadIdx.x) * 4;
    float4 v = *(const float4*)(X + i);
    uint32_t h0, h1, l0, l1;
    split2(v.x, v.y, h0, l0);
    split2(v.z, v.w, h1, l1);
    *(uint2*)&g_x_hi[i] = make_uint2(h0, h1);
    *(uint2*)&g_x_lo[i] = make_uint2(l0, l1);
}
__global__ void __launch_bounds__(256) split_w_k(const float* __restrict__ WQ,
                                                 const float* __restrict__ WK,
                                                 const float* __restrict__ WV) {
    const int n = blockIdx.x, k = threadIdx.x;
    const float* src;
    int nn, WN;
    if (n < 256)      { src = WQ; nn = n;       WN = 256; }
    else if (n < 512) { src = WK; nn = n - 256; WN = 256; }
    else              { src = WV; nn = n - 512; WN = 512; }
    float x = src[(size_t)k * WN + nn];
    __nv_bfloat16 h, l;
    split1(x, h, l);
    g_w_hi[(size_t)n * 256 + k] = h;
    g_w_lo[(size_t)n * 256 + k] = l;
}

// zero-fill score tiles outside the decay band (exact fp32 underflow zeros)
__global__ void __launch_bounds__(256) score_zero(float* __restrict__ score) {
    const int bhq = blockIdx.z, lbq = blockIdx.y, mbq = blockIdx.x;
    const int d = lbq - mbq;
    if (d >= 0 && d <= 8) return;
    float* outp = score + ((size_t)bhq * LNc + (size_t)lbq * 128) * LNc + mbq * 128;
    const float4 z = make_float4(0.f, 0.f, 0.f, 0.f);
    const int tid = threadIdx.x;
#pragma unroll
    for (int i = 0; i < 16; i++) {
        const int idx = i * 256 + tid;
        const int r = idx >> 5, c4 = (idx & 31) * 4;
        *(float4*)(outp + (size_t)r * LNc + c4) = z;
    }
}

// ---------------- unified GEMM ---------------------------------------------
// MODE: 0=proj Q, 1=proj K, 2=proj V, 3=score, 4=vt
template <int MODE>
__global__ void __launch_bounds__(256, 1)
gemm_u(const __grid_constant__ CUtensorMap tAh, const __grid_constant__ CUtensorMap tAl,
       const __grid_constant__ CUtensorMap tBh, const __grid_constant__ CUtensorMap tBl,
       float* __restrict__ score, float* __restrict__ vtout) {
    extern __shared__ char smem[];
    const int tid = threadIdx.x;
    const int wid = tid >> 5, lane = tid & 31;

    int nbase = 0, mtile = 0, bh = 0, lb = 0, mb = 0, diag = 0;
    int dmax = 0, mb0 = 0, S = 4, yA = 0, yB = 0;
    if constexpr (MODE <= 2) {
        nbase = blockIdx.x * 128;
        mtile = blockIdx.y;
        yA = mtile * 128;
        yB = ((MODE == 0) ? 0 : (MODE == 1) ? 256 : 512) + nbase;
    } else if constexpr (MODE == 3) {
        bh = blockIdx.z; lb = blockIdx.y; diag = blockIdx.x;
        mb = lb - diag;
        if (mb < 0) return;
        yA = bh * 2048 + lb * 128;
        yB = bh * 2048 + mb * 128;
    } else {
        bh = blockIdx.z; lb = blockIdx.y; nbase = blockIdx.x * 128;
        dmax = (lb < 8) ? lb : 8;
        mb0 = lb - dmax;
        S = 2 * (dmax + 1);
        yB = bh * 512 + nbase;
    }

#if TC_OK
    const uint32_t smem_base = s2u(smem);
    if (wid == 0) TC_ALLOC(smem_base, 128);
    if (tid == 0) {
#pragma unroll
        for (int b = 0; b < NBUF; b++) {
            MBAR_INIT(smem_base + 16 + b * 8, 1);   // full
            MBAR_INIT(smem_base + 40 + b * 8, 1);   // empty
        }
    }
    __syncthreads();
    uint32_t tmem;
    asm volatile("ld.shared.b32 %0, [%1];" : "=r"(tmem) : "r"(smem_base));

    if (tid == 0) {
        auto issue = [&](int s, int b) {
            int xa, ya, xb, yb;
            if constexpr (MODE <= 3) { xa = s * 64; ya = yA; }
            else {
                xa = (s & 1) * 64;
                ya = ((bh * 16 + lb) * 9 + (dmax - (s >> 1))) * 128;
            }
            if constexpr (MODE <= 3) { xb = s * 64; yb = yB; }
            else { xb = mb0 * 128 + s * 64; yb = yB; }
            const uint32_t dst  = smem_base + SMEM_BUF0 + b * STAGE_BYTES;
            const uint32_t full = smem_base + 16 + b * 8;
            EXPECT_TX(full, STAGE_BYTES);
            tma2d(dst,         &tAh, xa, ya, full);
            tma2d(dst + 16384, &tAl, xa, ya, full);
            tma2d(dst + 32768, &tBh, xb, yb, full);
            tma2d(dst + 49152, &tBl, xb, yb, full);
        };
        const int pre = (S < NBUF) ? S : NBUF;
        for (int s = 0; s < pre; s++) issue(s, s);
        int phF[NBUF] = {0, 0, 0}, phE[NBUF] = {0, 0, 0};
        for (int s = 0; s < S; s++) {
            const int b = s % NBUF;
            MBAR_WAIT(smem_base + 16 + b * 8, phF[b]); phF[b] ^= 1;
            const uint32_t base = smem_base + SMEM_BUF0 + b * STAGE_BYTES;
            const uint64_t ah = mkdesc(base);
            const uint64_t al = mkdesc(base + 16384);
            const uint64_t bhd = mkdesc(base + 32768);
            const uint64_t bld = mkdesc(base + 49152);
#pragma unroll
            for (int ks = 0; ks < 4; ks++) {
                mma_bf16(tmem, ah + ks * 2, bhd + ks * 2, IDESC_BF16,
                         (s > 0 || ks > 0) ? 1u : 0u);
                mma_bf16(tmem, ah + ks * 2, bld + ks * 2, IDESC_BF16, 1u);
                mma_bf16(tmem, al + ks * 2, bhd + ks * 2, IDESC_BF16, 1u);
            }
            TC_COMMIT(smem_base + 40 + b * 8);
            if (s + NBUF < S) {
                MBAR_WAIT(smem_base + 40 + b * 8, phE[b]); phE[b] ^= 1;
                issue(s + NBUF, b);
            }
        }
        const int bl_ = (S - 1) % NBUF;
        MBAR_WAIT(smem_base + 40 + bl_ * 8, phE[bl_]);
    }
    __syncthreads();
    TC_FENCE_AFTER();

    // ------------- epilogue: TMEM -> transform -> direct global stores -----
    if (wid < 4) {
        const int rowIdx = wid * 32 + lane;
#pragma unroll 1
        for (int ch = 0; ch < 4; ch++) {
            uint32_t r[32];
            TC_LD_X32(r, tmem + ch * 32);
            TC_WAIT_LD();

            if constexpr (MODE == 0 || MODE == 1) {
                const int grow = mtile * 128 + rowIdx;
                const int l = grow & (LNc - 1);
                uint32_t hi[16], lo[16];
#pragma unroll
                for (int c = 0; c < 32; c += 2) {
                    const int col = nbase + ch * 32 + c;
                    float theta = exp2f(-(float)(col >> 1) *
                                        (13.287712379549449f / 127.0f));
                    float sn, cs;
                    sincosf((float)l * theta, &sn, &cs);
                    float e = __uint_as_float(r[c]);
                    float o = __uint_as_float(r[c + 1]);
                    float ne, no;
                    if (MODE == 0) { ne = e * cs - o * sn; no = o * cs + e * sn; }
                    else           { ne = e * cs + o * sn; no = o * cs - e * sn; }
                    split2(ne, no, hi[c >> 1], lo[c >> 1]);
                }
                __nv_bfloat16* dh = (MODE == 0) ? g_q_hi : g_k_hi;
                __nv_bfloat16* dl = (MODE == 0) ? g_q_lo : g_k_lo;
                const size_t base = (size_t)grow * 256 + nbase + ch * 32;
#pragma unroll
                for (int q4 = 0; q4 < 4; q4++) {
                    *(uint4*)&dh[base + q4 * 8] = ((uint4*)hi)[q4];
                    *(uint4*)&dl[base + q4 * 8] = ((uint4*)lo)[q4];
                }
            } else if constexpr (MODE == 2) {
                const int mrow = mtile * 128 + rowIdx;
                const int bhv = mrow >> 11, mloc = mrow & (LNc - 1);
#pragma unroll
                for (int c = 0; c < 32; c++) {
                    const int n = nbase + ch * 32 + c;
                    __nv_bfloat16 h, l;
                    split1(__uint_as_float(r[c]), h, l);
                    const size_t idx = ((size_t)bhv * 512 + n) * 2048 + mloc;
                    g_vt_hi[idx] = h;
                    g_vt_lo[idx] = l;
                }
            } else if constexpr (MODE == 3) {
                const int l = lb * 128 + rowIdx;
                const float gpl = exp2f((float)(l + 1) * LOG2G);
                const float scale = 0.0625f / ((1.0f - gpl) * 10.0f);
                float v[32];
#pragma unroll
                for (int c = 0; c < 32; c++) {
                    const int m = mb * 128 + ch * 32 + c;
                    float w = (m <= l) ? exp2f((float)(l - m) * LOG2G) * scale : 0.f;
                    v[c] = __uint_as_float(r[c]) * w;
                }
                float* outp = score + ((size_t)bh * LNc + l) * LNc + mb * 128 + ch * 32;
#pragma unroll
                for (int c4 = 0; c4 < 32; c4 += 4)
                    *(float4*)(outp + c4) = make_float4(v[c4], v[c4 + 1],
                                                        v[c4 + 2], v[c4 + 3]);
                uint32_t hi[16], lo[16];
#pragma unroll
                for (int c = 0; c < 32; c += 2)
                    split2(v[c], v[c + 1], hi[c >> 1], lo[c >> 1]);
                const int tile = (bh * 16 + lb) * 9 + diag;
                const size_t sbase = ((size_t)tile * 128 + rowIdx) * 128 + ch * 32;
#pragma unroll
                for (int q4 = 0; q4 < 4; q4++) {
                    *(uint4*)&g_s_hi[sbase + q4 * 8] = ((uint4*)hi)[q4];
                    *(uint4*)&g_s_lo[sbase + q4 * 8] = ((uint4*)lo)[q4];
                }
            } else {
                const int l = lb * 128 + rowIdx;
                float* outp = vtout + ((size_t)bh * LNc + l) * VDc + nbase + ch * 32;
#pragma unroll
                for (int c4 = 0; c4 < 32; c4 += 4)
                    *(float4*)(outp + c4) = make_float4(
                        __uint_as_float(r[c4]),     __uint_as_float(r[c4 + 1]),
                        __uint_as_float(r[c4 + 2]), __uint_as_float(r[c4 + 3]));
            }
        }
    }
    __syncthreads();
    if (wid == 0) {
        TC_RELINQ();
        TC_DEALLOC(tmem, 128);
    }

#else
    // ----------------- SIMT fallback (non-arch-specific pass) --------------
    float* As = (float*)smem;          // [8][128]
    float* Bs = As + 8 * 128;          // [8][128]
    const int tx = tid & 15, ty = tid >> 4;
    const int arow = tid >> 1, acol = (tid & 1) * 4;

    float acc[8][8];
#pragma unroll
    for (int i = 0; i < 8; i++)
#pragma unroll
        for (int j = 0; j < 8; j++) acc[i][j] = 0.f;

    const int Klen = S * 64;
    const __nv_bfloat16 *Ah, *Al, *Bh2, *Bl2;
    size_t sA = 256, sB = 256;
    if constexpr (MODE <= 2) { Ah = g_x_hi; Al = g_x_lo; Bh2 = g_w_hi; Bl2 = g_w_lo; }
    else if constexpr (MODE == 3) { Ah = g_q_hi; Al = g_q_lo; Bh2 = g_k_hi; Bl2 = g_k_lo; }
    else { Ah = g_s_hi; Al = g_s_lo; Bh2 = g_vt_hi; Bl2 = g_vt_lo; sA = 128; sB = 2048; }

    for (int k0 = 0; k0 < Klen; k0 += 8) {
        // A row base
        size_t aIdx;
        if constexpr (MODE <= 2) aIdx = (size_t)(mtile * 128 + arow) * sA + k0 + acol;
        else if constexpr (MODE == 3) aIdx = (size_t)(yA + arow) * sA + k0 + acol;
        else {
            const int trow = ((bh * 16 + lb) * 9 + (dmax - (k0 >> 7))) * 128 + arow;
            aIdx = (size_t)trow * sA + (k0 & 127) + acol;
        }
        size_t bIdx;
        if constexpr (MODE <= 3) bIdx = (size_t)(yB + arow) * sB + k0 + acol;
        else bIdx = (size_t)(yB + arow) * sB + mb0 * 128 + k0 + acol;

        float av[4], bv[4];
#pragma unroll
        for (int j = 0; j < 4; j++) {
            av[j] = joinf(Ah, Al, aIdx + j);
            bv[j] = joinf(Bh2, Bl2, bIdx + j);
        }
        __syncthreads();
#pragma unroll
        for (int j = 0; j < 4; j++) {
            As[(acol + j) * 128 + arow] = av[j];
            Bs[(acol + j) * 128 + arow] = bv[j];
        }
        __syncthreads();
#pragma unroll
        for (int kk = 0; kk < 8; kk++) {
            float4 a0 = *(const float4*)&As[kk * 128 + ty * 4];
            float4 a1 = *(const float4*)&As[kk * 128 + 64 + ty * 4];
            float4 b0 = *(const float4*)&Bs[kk * 128 + tx * 4];
            float4 b1 = *(const float4*)&Bs[kk * 128 + 64 + tx * 4];
            float a[8] = {a0.x, a0.y, a0.z, a0.w, a1.x, a1.y, a1.z, a1.w};
            float bb[8] = {b0.x, b0.y, b0.z, b0.w, b1.x, b1.y, b1.z, b1.w};
#pragma unroll
            for (int i = 0; i < 8; i++)
#pragma unroll
                for (int j = 0; j < 8; j++) acc[i][j] = fmaf(a[i], bb[j], acc[i][j]);
        }
    }

#pragma unroll
    for (int i = 0; i < 8; i++) {
        const int rloc = (i < 4) ? (ty * 4 + i) : (64 + ty * 4 + (i - 4));
#pragma unroll
        for (int j = 0; j < 8; j++) {
            const int cloc = (j < 4) ? (tx * 4 + j) : (64 + tx * 4 + (j - 4));
            float x = acc[i][j];
            if constexpr (MODE == 0 || MODE == 1) {
                if ((j & 1) == 0) {
                    const int grow = mtile * 128 + rloc;
                    const int l = grow & (LNc - 1);
                    const int col = nbase + cloc;
                    float theta = exp2f(-(float)(col >> 1) *
                                        (13.287712379549449f / 127.0f));
                    float sn, cs;
                    sincosf((float)l * theta, &sn, &cs);
                    float e = acc[i][j], o = acc[i][j + 1];
                    float ne, no;
                    if (MODE == 0) { ne = e * cs - o * sn; no = o * cs + e * sn; }
                    else           { ne = e * cs + o * sn; no = o * cs - e * sn; }
                    __nv_bfloat16 h0, l0, h1, l1;
                    split1(ne, h0, l0); split1(no, h1, l1);
                    __nv_bfloat16* dh = (MODE == 0) ? g_q_hi : g_k_hi;
                    __nv_bfloat16* dl = (MODE == 0) ? g_q_lo : g_k_lo;
                    const size_t bidx = (size_t)grow * 256 + col;
                    dh[bidx] = h0; dh[bidx + 1] = h1;
                    dl[bidx] = l0; dl[bidx + 1] = l1;
                }
            } else if constexpr (MODE == 2) {
                const int mrow = mtile * 128 + rloc;
                const int bhv = mrow >> 11, mloc = mrow & (LNc - 1);
                __nv_bfloat16 h, l;
                split1(x, h, l);
                const size_t idx = ((size_t)bhv * 512 + nbase + cloc) * 2048 + mloc;
                g_vt_hi[idx] = h; g_vt_lo[idx] = l;
            } else if constexpr (MODE == 3) {
                const int l = lb * 128 + rloc;
                const int m = mb * 128 + cloc;
                const float gpl = exp2f((float)(l + 1) * LOG2G);
                const float scale = 0.0625f / ((1.0f - gpl) * 10.0f);
                float w = (m <= l) ? exp2f((float)(l - m) * LOG2G) * scale : 0.f;
                float v = x * w;
                score[((size_t)bh * LNc + l) * LNc + m] = v;
                __nv_bfloat16 h, lo_;
                split1(v, h, lo_);
                const int tile = (bh * 16 + lb) * 9 + diag;
                const size_t sbase = ((size_t)tile * 128 + rloc) * 128 + cloc;
                g_s_hi[sbase] = h; g_s_lo[sbase] = lo_;
            } else {
                vtout[((size_t)bh * LNc + lb * 128 + rloc) * VDc + nbase + cloc] = x;
            }
        }
    }
#endif
}

// ---------------- host ------------------------------------------------------
typedef CUresult (*EncodeFn)(CUtensorMap*, CUtensorMapDataType, cuuint32_t, void*,
                             const cuuint64_t*, const cuuint64_t*, const cuuint32_t*,
                             const cuuint32_t*, CUtensorMapInterleave, CUtensorMapSwizzle,
                             CUtensorMapL2promotion, CUtensorMapFloatOOBfill);

static void make_map(EncodeFn fn, CUtensorMap* m, void* base,
                     uint64_t d0, uint64_t d1, uint64_t strideB) {
    cuuint64_t dims[2]    = {d0, d1};
    cuuint64_t strides[1] = {strideB};
    cuuint32_t box[2]     = {64, 128};
    cuuint32_t es[2]      = {1, 1};
    fn(m, CU_TENSOR_MAP_DATA_TYPE_BFLOAT16, 2, base, dims, strides, box, es,
       CU_TENSOR_MAP_INTERLEAVE_NONE, CU_TENSOR_MAP_SWIZZLE_128B,
       CU_TENSOR_MAP_L2_PROMOTION_L2_128B, CU_TENSOR_MAP_FLOAT_OOB_FILL_NONE);
}

extern "C" void kernel_launch(void* const* d_in, const int* in_sizes, int n_in,
                              void* d_out, int out_size) {
    const float* X  = (const float*)d_in[0];
    const float* WQ = (const float*)d_in[1];
    const float* WK = (const float*)d_in[2];
    const float* WV = (const float*)d_in[3];

    float* out       = (float*)d_out;
    float* out_vt    = out;                           // [BH, L, VD]
    float* out_score = out + (size_t)BHc * LNc * VDc; // [BH, L, L]

    EncodeFn enc = nullptr;
    cudaDriverEntryPointQueryResult qr;
    cudaGetDriverEntryPoint("cuTensorMapEncodeTiled", (void**)&enc,
                            cudaEnableDefault, &qr);

    void *xh, *xl, *wh, *wl, *qh, *ql, *kh, *kl, *vh, *vl, *sh, *sl;
    cudaGetSymbolAddress(&xh, g_x_hi);  cudaGetSymbolAddress(&xl, g_x_lo);
    cudaGetSymbolAddress(&wh, g_w_hi);  cudaGetSymbolAddress(&wl, g_w_lo);
    cudaGetSymbolAddress(&qh, g_q_hi);  cudaGetSymbolAddress(&ql, g_q_lo);
    cudaGetSymbolAddress(&kh, g_k_hi);  cudaGetSymbolAddress(&kl, g_k_lo);
    cudaGetSymbolAddress(&vh, g_vt_hi); cudaGetSymbolAddress(&vl, g_vt_lo);
    cudaGetSymbolAddress(&sh, g_s_hi);  cudaGetSymbolAddress(&sl, g_s_lo);

    CUtensorMap mxh, mxl, mwh, mwl, mqh, mql, mkh, mkl, mvh, mvl, msh, msl;
    make_map(enc, &mxh, xh, 256, 32768, 512);
    make_map(enc, &mxl, xl, 256, 32768, 512);
    make_map(enc, &mwh, wh, 256, 1024, 512);
    make_map(enc, &mwl, wl, 256, 1024, 512);
    make_map(enc, &mqh, qh, 256, 32768, 512);
    make_map(enc, &mql, ql, 256, 32768, 512);
    make_map(enc, &mkh, kh, 256, 32768, 512);
    make_map(enc, &mkl, kl, 256, 32768, 512);
    make_map(enc, &mvh, vh, 2048, 8192, 4096);
    make_map(enc, &mvl, vl, 2048, 8192, 4096);
    make_map(enc, &msh, sh, 128, 294912, 256);
    make_map(enc, &msl, sl, 128, 294912, 256);

    cudaFuncSetAttribute(gemm_u<0>, cudaFuncAttributeMaxDynamicSharedMemorySize, SMEM_TOTAL);
    cudaFuncSetAttribute(gemm_u<1>, cudaFuncAttributeMaxDynamicSharedMemorySize, SMEM_TOTAL);
    cudaFuncSetAttribute(gemm_u<2>, cudaFuncAttributeMaxDynamicSharedMemorySize, SMEM_TOTAL);
    cudaFuncSetAttribute(gemm_u<3>, cudaFuncAttributeMaxDynamicSharedMemorySize, SMEM_TOTAL);
    cudaFuncSetAttribute(gemm_u<4>, cudaFuncAttributeMaxDynamicSharedMemorySize, SMEM_TOTAL);

    split_x_k<<<8192, 256>>>(X);
    split_w_k<<<1024, 256>>>(WQ, WK, WV);

    gemm_u<0><<<dim3(2, 256), 256, SMEM_TOTAL>>>(mxh, mxl, mwh, mwl, nullptr, nullptr);
    gemm_u<1><<<dim3(2, 256), 256, SMEM_TOTAL>>>(mxh, mxl, mwh, mwl, nullptr, nullptr);
    gemm_u<2><<<dim3(4, 256), 256, SMEM_TOTAL>>>(mxh, mxl, mwh, mwl, nullptr, nullptr);
    score_zero<<<dim3(16, 16, 16), 256>>>(out_score);
    gemm_u<3><<<dim3(9, 16, 16), 256, SMEM_TOTAL>>>(mqh, mql, mkh, mkl, out_score, nullptr);
    gemm_u<4><<<dim3(4, 16, 16), 256, SMEM_TOTAL>>>(msh, msl, mvh, mvl, out_score, out_vt);
}

// round 5
// speedup vs baseline: 3.7418x; 1.0459x over previous
#include <cuda_runtime.h>
#include <cuda_bf16.h>
#include <cuda.h>
#include <cstdint>

#define BHc 16
#define LNc 2048
#define DMc 256
#define VDc 512
#define LOG2G (-0.15200309344504995f)
#define GINVf (1.1111111111111112f)

#if defined(__CUDA_ARCH_FEAT_SM103_ALL) || defined(__CUDA_ARCH_FEAT_SM100_ALL) || \
    (defined(__CUDA_ARCH_SPECIFIC__) && (__CUDA_ARCH_SPECIFIC__ >= 1000))
#define TC_OK 1
#else
#define TC_OK 0
#endif

// ---------------- scratch (bf16 hi/lo split pairs) -------------------------
__device__ __align__(1024) __nv_bfloat16 g_x_hi [32768u * 256];
__device__ __align__(1024) __nv_bfloat16 g_x_lo [32768u * 256];
__device__ __align__(1024) __nv_bfloat16 g_w_hi [1024u  * 256];   // [n:1024][k:256] (Q|K|V)
__device__ __align__(1024) __nv_bfloat16 g_w_lo [1024u  * 256];
__device__ __align__(1024) __nv_bfloat16 g_q_hi [32768u * 256];
__device__ __align__(1024) __nv_bfloat16 g_q_lo [32768u * 256];
__device__ __align__(1024) __nv_bfloat16 g_k_hi [32768u * 256];
__device__ __align__(1024) __nv_bfloat16 g_k_lo [32768u * 256];
__device__ __align__(1024) __nv_bfloat16 g_vt_hi[8192u  * 2048];  // [bh*512+n][m]
__device__ __align__(1024) __nv_bfloat16 g_vt_lo[8192u  * 2048];
__device__ __align__(1024) __nv_bfloat16 g_s_hi [(size_t)294912 * 128]; // [(bh*16+lb)*9+diag tiles][128][128]
__device__ __align__(1024) __nv_bfloat16 g_s_lo [(size_t)294912 * 128];

#define NBUF 3
#define STAGE_BYTES 65536          // a_hi,a_lo,b_hi,b_lo @ 16KB each
#define SMEM_BUF0   1024
#define SMEM_TOTAL  (SMEM_BUF0 + NBUF * STAGE_BYTES)

// ---------------- small helpers --------------------------------------------
static __device__ __forceinline__ uint32_t s2u(const void* p) {
    uint32_t a;
    asm("{ .reg .u64 t; cvta.to.shared.u64 t, %1; cvt.u32.u64 %0, t; }"
        : "=r"(a) : "l"(p));
    return a;
}
static __device__ __forceinline__ void split2(float x0, float x1,
                                              uint32_t& h, uint32_t& l) {
    asm("cvt.rn.bf16x2.f32 %0, %1, %2;" : "=r"(h) : "f"(x1), "f"(x0));
    float h0 = __uint_as_float(h << 16);
    float h1 = __uint_as_float(h & 0xffff0000u);
    asm("cvt.rn.bf16x2.f32 %0, %1, %2;" : "=r"(l) : "f"(x1 - h1), "f"(x0 - h0));
}
static __device__ __forceinline__ void split1(float x, __nv_bfloat16& h,
                                              __nv_bfloat16& l) {
    h = __float2bfloat16_rn(x);
    l = __float2bfloat16_rn(x - __bfloat162float(h));
}
static __device__ __forceinline__ float joinf(const __nv_bfloat16* hi,
                                              const __nv_bfloat16* lo, size_t i) {
    return __bfloat162float(hi[i]) + __bfloat162float(lo[i]);
}

#if TC_OK
static __device__ __forceinline__ uint64_t mkdesc(uint32_t addr) {
    const uint64_t base = (2ull << 61) | (1ull << 46) | (64ull << 32) | (1ull << 16);
    return base | ((uint64_t)(addr >> 4) & 0x3FFF);
}
static __device__ __forceinline__ void mma_bf16(uint32_t d, uint64_t a, uint64_t b,
                                                uint32_t idesc, uint32_t en) {
    asm volatile(
        "{\n\t.reg .pred p;\n\tsetp.ne.u32 p, %4, 0;\n\t"
        "tcgen05.mma.cta_group::1.kind::f16 [%0], %1, %2, %3, p;\n\t}"
        :: "r"(d), "l"(a), "l"(b), "r"(idesc), "r"(en) : "memory");
}
static __device__ __forceinline__ void tma2d(uint32_t dst, const CUtensorMap* m,
                                             int x, int y, uint32_t mbar) {
    asm volatile(
        "cp.async.bulk.tensor.2d.shared::cta.global.tile.mbarrier::complete_tx::bytes "
        "[%0], [%1, {%2, %3}], [%4];"
        :: "r"(dst), "l"((const void*)m), "r"(x), "r"(y), "r"(mbar) : "memory");
}
#define TC_ALLOC(sm, n)  asm volatile("tcgen05.alloc.cta_group::1.sync.aligned.shared::cta.b32 [%0], %1;" :: "r"(sm), "r"(n) : "memory")
#define TC_DEALLOC(t, n) asm volatile("tcgen05.dealloc.cta_group::1.sync.aligned.b32 %0, %1;" :: "r"(t), "r"(n))
#define TC_RELINQ()      asm volatile("tcgen05.relinquish_alloc_permit.cta_group::1.sync.aligned;")
#define TC_COMMIT(mb)    asm volatile("tcgen05.commit.cta_group::1.mbarrier::arrive::one.shared::cluster.b64 [%0];" :: "r"(mb) : "memory")
#define TC_FENCE_AFTER() asm volatile("tcgen05.fence::after_thread_sync;" ::: "memory")
#define TC_FENCE_BEFORE() asm volatile("tcgen05.fence::before_thread_sync;" ::: "memory")
#define TC_WAIT_LD()     asm volatile("tcgen05.wait::ld.sync.aligned;" ::: "memory")
#define MBAR_INIT(mb, c) asm volatile("mbarrier.init.shared.b64 [%0], %1;" :: "r"(mb), "r"(c) : "memory")
#define MBAR_ARRIVE(mb)  asm volatile("mbarrier.arrive.shared.b64 _, [%0];" :: "r"(mb) : "memory")
#define EXPECT_TX(mb, n) asm volatile("mbarrier.arrive.expect_tx.shared.b64 _, [%0], %1;" :: "r"(mb), "r"(n) : "memory")

#define MBAR_WAIT(mb, ph) do {                                                   \
    uint32_t _m = (mb), _p = (ph), _d;                                           \
    asm volatile("{\n\t.reg .pred p;\n\t"                                        \
        "mbarrier.try_wait.parity.acquire.cta.shared::cta.b64 p, [%1], %2;\n\t"  \
        "selp.b32 %0, 1, 0, p;\n\t}"                                             \
        : "=r"(_d) : "r"(_m), "r"(_p) : "memory");                               \
    if (!_d) {                                                                   \
        asm volatile("{\n\t.reg .pred P1;\n\t"                                   \
            "W_%=:\n\t"                                                          \
            "mbarrier.try_wait.parity.acquire.cta.shared::cta.b64 P1, [%0], %1, 0x989680;\n\t" \
            "@P1 bra.uni D_%=;\n\tbra.uni W_%=;\n\tD_%=:\n\t}"                   \
            :: "r"(_m), "r"(_p) : "memory");                                     \
    }                                                                            \
} while (0)

#define TC_LD_X32(r, ta)                                                         \
    asm volatile("tcgen05.ld.sync.aligned.32x32b.x32.b32 "                       \
        "{%0,%1,%2,%3,%4,%5,%6,%7,%8,%9,%10,%11,%12,%13,%14,%15,"                \
        "%16,%17,%18,%19,%20,%21,%22,%23,%24,%25,%26,%27,%28,%29,%30,%31}, [%32];" \
        : "=r"((r)[0]),"=r"((r)[1]),"=r"((r)[2]),"=r"((r)[3]),                   \
          "=r"((r)[4]),"=r"((r)[5]),"=r"((r)[6]),"=r"((r)[7]),                   \
          "=r"((r)[8]),"=r"((r)[9]),"=r"((r)[10]),"=r"((r)[11]),                 \
          "=r"((r)[12]),"=r"((r)[13]),"=r"((r)[14]),"=r"((r)[15]),               \
          "=r"((r)[16]),"=r"((r)[17]),"=r"((r)[18]),"=r"((r)[19]),               \
          "=r"((r)[20]),"=r"((r)[21]),"=r"((r)[22]),"=r"((r)[23]),               \
          "=r"((r)[24]),"=r"((r)[25]),"=r"((r)[26]),"=r"((r)[27]),               \
          "=r"((r)[28]),"=r"((r)[29]),"=r"((r)[30]),"=r"((r)[31])                \
        : "r"(ta))

#define IDESC_BF16 0x08200490u
#endif

// ---------------- prep kernels ---------------------------------------------
__global__ void __launch_bounds__(256) split_x_k(const float* __restrict__ X) {
    size_t i = ((size_t)blockIdx.x * 256 + threadIdx.x) * 4;
    float4 v = *(const float4*)(X + i);
    uint32_t h0, h1, l0, l1;
    split2(v.x, v.y, h0, l0);
    split2(v.z, v.w, h1, l1);
    *(uint2*)&g_x_hi[i] = make_uint2(h0, h1);
    *(uint2*)&g_x_lo[i] = make_uint2(l0, l1);
}
__global__ void __launch_bounds__(256) split_w_k(const float* __restrict__ WQ,
                                                 const float* __restrict__ WK,
                                                 const float* __restrict__ WV) {
    const int n = blockIdx.x, k = threadIdx.x;
    const float* src;
    int nn, WN;
    if (n < 256)      { src = WQ; nn = n;       WN = 256; }
    else if (n < 512) { src = WK; nn = n - 256; WN = 256; }
    else              { src = WV; nn = n - 512; WN = 512; }
    float x = src[(size_t)k * WN + nn];
    __nv_bfloat16 h, l;
    split1(x, h, l);
    g_w_hi[(size_t)n * 256 + k] = h;
    g_w_lo[(size_t)n * 256 + k] = l;
}

// ---------------- unified pipelined GEMM ------------------------------------
// MODE 0: fused QKV projection, tiles (nb 0..7, mt 0..255), TPC=4
// MODE 1: score incl. zero tiles,  tiles (bh, lb, mb 0..15), TPC=4
// MODE 2: vt,                      tiles (bh, lb, nb 0..3),  TPC=2
template <int MODE>
__global__ void __launch_bounds__(256, 1)
gemm_p(const __grid_constant__ CUtensorMap tAh, const __grid_constant__ CUtensorMap tAl,
       const __grid_constant__ CUtensorMap tBh, const __grid_constant__ CUtensorMap tBl,
       float* __restrict__ score, float* __restrict__ vtout) {
    constexpr int TPC = (MODE == 2) ? 2 : 4;
    const int tid = threadIdx.x;
    const int tileBase = blockIdx.x * TPC;

#if TC_OK
    extern __shared__ char smem[];
    const uint32_t smem_base = s2u(smem);
    const int wid = tid >> 5, lane = tid & 31;

#define BAR_FULL(b)  (smem_base + 16 + (b) * 8)
#define BAR_EMPTY(b) (smem_base + 40 + (b) * 8)
#define BAR_AFULL(b) (smem_base + 64 + (b) * 8)
#define BAR_AFREE(b) (smem_base + 80 + (b) * 8)

    if (wid == 0) TC_ALLOC(smem_base, 256);
    if (tid == 0) {
#pragma unroll
        for (int b = 0; b < NBUF; b++) {
            MBAR_INIT(BAR_FULL(b), 1);
            MBAR_INIT(BAR_EMPTY(b), 1);
        }
#pragma unroll
        for (int b = 0; b < 2; b++) {
            MBAR_INIT(BAR_AFULL(b), 1);
            MBAR_INIT(BAR_AFREE(b), 128);
        }
    }
    __syncthreads();
    uint32_t tmem;
    asm volatile("ld.shared.b32 %0, [%1];" : "=r"(tmem) : "r"(smem_base));

    auto band_of = [&](int t) -> bool {
        if constexpr (MODE == 1) {
            const int tile = tileBase + t;
            const int mb = tile & 15, lb = (tile >> 4) & 15;
            const int d = lb - mb;
            return d >= 0 && d <= 8;
        }
        return true;
    };
    auto S_of = [&](int t) -> int {
        if constexpr (MODE == 2) {
            const int tile = tileBase + t;
            const int lb = (tile >> 2) & 15;
            const int dmax = lb < 8 ? lb : 8;
            return 2 * (dmax + 1);
        }
        return 4;
    };

    // ======================= producer (warp 7, lane 0) ======================
    if (tid == 224) {
        auto issueTMA = [&](int t, int s, int b) {
            const int tile = tileBase + t;
            int xa, ya, xb, yb;
            if constexpr (MODE == 0) {
                xa = s * 64; ya = (tile & 255) * 128;
                xb = s * 64; yb = (tile >> 8) * 128;
            } else if constexpr (MODE == 1) {
                const int mb = tile & 15, lb = (tile >> 4) & 15, bh = tile >> 8;
                xa = s * 64; ya = bh * 2048 + lb * 128;
                xb = s * 64; yb = bh * 2048 + mb * 128;
            } else {
                const int nb = tile & 3, lb = (tile >> 2) & 15, bh = tile >> 6;
                const int dmax = lb < 8 ? lb : 8, mb0 = lb - dmax;
                xa = (s & 1) * 64;
                ya = ((bh * 16 + lb) * 9 + (dmax - (s >> 1))) * 128;
                xb = mb0 * 128 + s * 64;
                yb = bh * 512 + nb * 128;
            }
            const uint32_t dst  = smem_base + SMEM_BUF0 + b * STAGE_BYTES;
            const uint32_t full = BAR_FULL(b);
            EXPECT_TX(full, STAGE_BYTES);
            tma2d(dst,         &tAh, xa, ya, full);
            tma2d(dst + 16384, &tAl, xa, ya, full);
            tma2d(dst + 32768, &tBh, xb, yb, full);
            tma2d(dst + 49152, &tBl, xb, yb, full);
        };
        auto adv = [&](int& t, int& s) {
            if (++s >= S_of(t)) {
                s = 0; t++;
                while (t < TPC && !band_of(t)) t++;
            }
        };

        int it = 0;
        while (it < TPC && !band_of(it)) it++;
        int is_ = 0;
        int g_issue = 0;
        int phF[NBUF] = {0, 0, 0}, phE[NBUF] = {0, 0, 0}, phFree[2] = {0, 0};

        while (it < TPC && g_issue < NBUF) {
            issueTMA(it, is_, g_issue % NBUF);
            g_issue++;
            adv(it, is_);
        }

        int g_mma = 0, bandIdx = 0;
        for (int t = 0; t < TPC; t++) {
            if (!band_of(t)) continue;
            const int accb = bandIdx & 1;
            if (bandIdx >= 2) { MBAR_WAIT(BAR_AFREE(accb), phFree[accb]); phFree[accb] ^= 1; }
            const int S_t = S_of(t);
            const uint32_t dacc = tmem + accb * 128;
            for (int s = 0; s < S_t; s++) {
                const int b = g_mma % NBUF;
                MBAR_WAIT(BAR_FULL(b), phF[b]); phF[b] ^= 1;
                const uint32_t base = smem_base + SMEM_BUF0 + b * STAGE_BYTES;
                const uint64_t ah  = mkdesc(base);
                const uint64_t al  = mkdesc(base + 16384);
                const uint64_t bhd = mkdesc(base + 32768);
                const uint64_t bld = mkdesc(base + 49152);
#pragma unroll
                for (int ks = 0; ks < 4; ks++) {
                    mma_bf16(dacc, ah + ks * 2, bhd + ks * 2, IDESC_BF16,
                             (s > 0 || ks > 0) ? 1u : 0u);
                    mma_bf16(dacc, ah + ks * 2, bld + ks * 2, IDESC_BF16, 1u);
                    mma_bf16(dacc, al + ks * 2, bhd + ks * 2, IDESC_BF16, 1u);
                }
                TC_COMMIT(BAR_EMPTY(b));
                if (s == S_t - 1) TC_COMMIT(BAR_AFULL(accb));
                g_mma++;
                if (it < TPC) {
                    const int b2 = g_issue % NBUF;
                    if (g_issue >= NBUF) { MBAR_WAIT(BAR_EMPTY(b2), phE[b2]); phE[b2] ^= 1; }
                    issueTMA(it, is_, b2);
                    g_issue++;
                    adv(it, is_);
                }
            }
            bandIdx++;
        }
    }

    // ======================= consumers (warps 0-3) ==========================
    if (tid < 128) {
        const int rowIdx = wid * 32 + lane;
        int bandIdx = 0;
        int phAcc[2] = {0, 0};
        for (int t = 0; t < TPC; t++) {
            const int tile = tileBase + t;
            if constexpr (MODE == 1) {
                const int mb = tile & 15, lb = (tile >> 4) & 15, bh = tile >> 8;
                const int d = lb - mb;
                if (d < 0 || d > 8) {   // zero tile: pure stores
                    float* rp = score + ((size_t)bh * 2048 + lb * 128 + tid) * 2048 + mb * 128;
                    const float4 z = make_float4(0.f, 0.f, 0.f, 0.f);
#pragma unroll
                    for (int c = 0; c < 32; c++) ((float4*)rp)[c] = z;
                    continue;
                }
            }
            const int accb = bandIdx & 1;
            MBAR_WAIT(BAR_AFULL(accb), phAcc[accb]); phAcc[accb] ^= 1;
            TC_FENCE_AFTER();

#pragma unroll 1
            for (int ch = 0; ch < 4; ch++) {
                uint32_t r[32];
                TC_LD_X32(r, tmem + accb * 128 + ch * 32);
                TC_WAIT_LD();

                if constexpr (MODE == 0) {
                    const int mt = tile & 255, nb = tile >> 8;
                    if (nb < 4) {   // Q or K: rotary + split store
                        const bool isQ = nb < 2;
                        const int colbase = (isQ ? nb : nb - 2) * 128 + ch * 32;
                        const int grow = mt * 128 + rowIdx;
                        const int l = grow & (LNc - 1);
                        uint32_t hi[16], lo[16];
#pragma unroll
                        for (int c = 0; c < 32; c += 2) {
                            const int col = colbase + c;
                            float theta = exp2f(-(float)(col >> 1) *
                                                (13.287712379549449f / 127.0f));
                            float sn, cs;
                            sincosf((float)l * theta, &sn, &cs);
                            float e = __uint_as_float(r[c]);
                            float o = __uint_as_float(r[c + 1]);
                            float ne, no;
                            if (isQ) { ne = e * cs - o * sn; no = o * cs + e * sn; }
                            else     { ne = e * cs + o * sn; no = o * cs - e * sn; }
                            split2(ne, no, hi[c >> 1], lo[c >> 1]);
                        }
                        __nv_bfloat16* dh = isQ ? g_q_hi : g_k_hi;
                        __nv_bfloat16* dl = isQ ? g_q_lo : g_k_lo;
                        const size_t basep = (size_t)grow * 256 + colbase;
#pragma unroll
                        for (int q4 = 0; q4 < 4; q4++) {
                            *(uint4*)&dh[basep + q4 * 8] = ((uint4*)hi)[q4];
                            *(uint4*)&dl[basep + q4 * 8] = ((uint4*)lo)[q4];
                        }
                    } else {        // V: transposed split store
                        const int mrow = mt * 128 + rowIdx;
                        const int bhv = mrow >> 11, mloc = mrow & (LNc - 1);
                        const int nbase = (nb - 4) * 128 + ch * 32;
#pragma unroll
                        for (int c = 0; c < 32; c++) {
                            __nv_bfloat16 h, l;
                            split1(__uint_as_float(r[c]), h, l);
                            const size_t idx = ((size_t)bhv * 512 + nbase + c) * 2048 + mloc;
                            g_vt_hi[idx] = h;
                            g_vt_lo[idx] = l;
                        }
                    }
                } else if constexpr (MODE == 1) {
                    const int mb = tile & 15, lb = (tile >> 4) & 15, bh = tile >> 8;
                    const int diag = lb - mb;
                    const int l = lb * 128 + rowIdx;
                    const float gpl = exp2f((float)(l + 1) * LOG2G);
                    const float scale = 0.0625f / ((1.0f - gpl) * 10.0f);
                    const int m0 = mb * 128 + ch * 32;
                    float v[32];
                    if (m0 > l) {
#pragma unroll
                        for (int c = 0; c < 32; c++) v[c] = 0.f;
                    } else {
                        float w = exp2f((float)(l - m0) * LOG2G) * scale;
#pragma unroll
                        for (int c = 0; c < 32; c++) {
                            v[c] = (m0 + c <= l) ? __uint_as_float(r[c]) * w : 0.f;
                            w *= GINVf;
                        }
                    }
                    float* outp = score + ((size_t)bh * LNc + l) * LNc + m0;
#pragma unroll
                    for (int c4 = 0; c4 < 32; c4 += 4)
                        *(float4*)(outp + c4) = make_float4(v[c4], v[c4 + 1],
                                                            v[c4 + 2], v[c4 + 3]);
                    uint32_t hi[16], lo[16];
#pragma unroll
                    for (int c = 0; c < 32; c += 2)
                        split2(v[c], v[c + 1], hi[c >> 1], lo[c >> 1]);
                    const int tile9 = (bh * 16 + lb) * 9 + diag;
                    const size_t sbase = ((size_t)tile9 * 128 + rowIdx) * 128 + ch * 32;
#pragma unroll
                    for (int q4 = 0; q4 < 4; q4++) {
                        *(uint4*)&g_s_hi[sbase + q4 * 8] = ((uint4*)hi)[q4];
                        *(uint4*)&g_s_lo[sbase + q4 * 8] = ((uint4*)lo)[q4];
                    }
                } else {
                    const int nb = tile & 3, lb = (tile >> 2) & 15, bh = tile >> 6;
                    const int l = lb * 128 + rowIdx;
                    float* outp = vtout + ((size_t)bh * LNc + l) * VDc + nb * 128 + ch * 32;
#pragma unroll
                    for (int c4 = 0; c4 < 32; c4 += 4)
                        *(float4*)(outp + c4) = make_float4(
                            __uint_as_float(r[c4]),     __uint_as_float(r[c4 + 1]),
                            __uint_as_float(r[c4 + 2]), __uint_as_float(r[c4 + 3]));
                }
            }
            TC_FENCE_BEFORE();
            MBAR_ARRIVE(BAR_AFREE(accb));
            bandIdx++;
        }
    }

    __syncthreads();
    if (wid == 0) {
        TC_RELINQ();
        TC_DEALLOC(tmem, 256);
    }

#else
    // ---------------- correct (slow) SIMT fallback for plain sm_103 pass ----
    for (int t = 0; t < TPC; t++) {
        const int tile = tileBase + t;
        if constexpr (MODE == 1) {
            const int mb = tile & 15, lb = (tile >> 4) & 15, bh = tile >> 8;
            const int d = lb - mb;
            if (d < 0 || d > 8) {
                for (int e = tid; e < 128 * 128; e += 256) {
                    const int i = e >> 7, j = e & 127;
                    score[((size_t)bh * LNc + lb * 128 + i) * LNc + mb * 128 + j] = 0.f;
                }
                continue;
            }
        }
        if constexpr (MODE == 0) {
            const int mt = tile & 255, nb = tile >> 8;
            if (nb < 4) {
                const bool isQ = nb < 2;
                const int colbase = (isQ ? nb : nb - 2) * 128;
                for (int e = tid; e < 128 * 64; e += 256) {
                    const int i = e >> 6, j = (e & 63) * 2;
                    float a0 = 0.f, a1 = 0.f;
                    const size_t ra = (size_t)(mt * 128 + i) * 256;
                    const size_t rb0 = (size_t)(nb * 128 + j) * 256;
#pragma unroll 4
                    for (int k = 0; k < 256; k++) {
                        float xv = joinf(g_x_hi, g_x_lo, ra + k);
                        a0 += xv * joinf(g_w_hi, g_w_lo, rb0 + k);
                        a1 += xv * joinf(g_w_hi, g_w_lo, rb0 + 256 + k);
                    }
                    const int l = (mt * 128 + i) & (LNc - 1);
                    const int col = colbase + j;
                    float theta = exp2f(-(float)(col >> 1) * (13.287712379549449f / 127.0f));
                    float sn, cs;
                    sincosf((float)l * theta, &sn, &cs);
                    float ne, no;
                    if (isQ) { ne = a0 * cs - a1 * sn; no = a1 * cs + a0 * sn; }
                    else     { ne = a0 * cs + a1 * sn; no = a1 * cs - a0 * sn; }
                    __nv_bfloat16 h0, l0, h1, l1;
                    split1(ne, h0, l0); split1(no, h1, l1);
                    __nv_bfloat16* dh = isQ ? g_q_hi : g_k_hi;
                    __nv_bfloat16* dl = isQ ? g_q_lo : g_k_lo;
                    const size_t bidx = (size_t)(mt * 128 + i) * 256 + col;
                    dh[bidx] = h0; dh[bidx + 1] = h1;
                    dl[bidx] = l0; dl[bidx + 1] = l1;
                }
            } else {
                for (int e = tid; e < 128 * 128; e += 256) {
                    const int i = e >> 7, j = e & 127;
                    float a0 = 0.f;
                    const size_t ra = (size_t)(mt * 128 + i) * 256;
                    const size_t rb = (size_t)(nb * 128 + j) * 256;
#pragma unroll 4
                    for (int k = 0; k < 256; k++)
                        a0 += joinf(g_x_hi, g_x_lo, ra + k) * joinf(g_w_hi, g_w_lo, rb + k);
                    const int mrow = mt * 128 + i;
                    const int bhv = mrow >> 11, mloc = mrow & (LNc - 1);
                    __nv_bfloat16 h, l;
                    split1(a0, h, l);
                    const size_t idx = ((size_t)bhv * 512 + (nb - 4) * 128 + j) * 2048 + mloc;
                    g_vt_hi[idx] = h; g_vt_lo[idx] = l;
                }
            }
        } else if constexpr (MODE == 1) {
            const int mb = tile & 15, lb = (tile >> 4) & 15, bh = tile >> 8;
            const int diag = lb - mb;
            for (int e = tid; e < 128 * 128; e += 256) {
                const int i = e >> 7, j = e & 127;
                float acc = 0.f;
                const size_t ra = ((size_t)bh * 2048 + lb * 128 + i) * 256;
                const size_t rb = ((size_t)bh * 2048 + mb * 128 + j) * 256;
#pragma unroll 4
                for (int k = 0; k < 256; k++)
                    acc += joinf(g_q_hi, g_q_lo, ra + k) * joinf(g_k_hi, g_k_lo, rb + k);
                const int l = lb * 128 + i, m = mb * 128 + j;
                const float gpl = exp2f((float)(l + 1) * LOG2G);
                const float scale = 0.0625f / ((1.0f - gpl) * 10.0f);
                float w = (m <= l) ? exp2f((float)(l - m) * LOG2G) * scale : 0.f;
                float v = acc * w;
                score[((size_t)bh * LNc + l) * LNc + m] = v;
                __nv_bfloat16 h, lo_;
                split1(v, h, lo_);
                const size_t sbase = ((size_t)((bh * 16 + lb) * 9 + diag) * 128 + i) * 128 + j;
                g_s_hi[sbase] = h; g_s_lo[sbase] = lo_;
            }
        } else {
            const int nb = tile & 3, lb = (tile >> 2) & 15, bh = tile >> 6;
            const int dmax = lb < 8 ? lb : 8, mb0 = lb - dmax;
            const int Kl = (dmax + 1) * 128;
            for (int e = tid; e < 128 * 128; e += 256) {
                const int i = e >> 7, j = e & 127;
                float acc = 0.f;
                const size_t rb = ((size_t)bh * 512 + nb * 128 + j) * 2048 + mb0 * 128;
#pragma unroll 4
                for (int k = 0; k < Kl; k++) {
                    const size_t ra = ((size_t)((bh * 16 + lb) * 9 + (dmax - (k >> 7))) * 128 + i) * 128 + (k & 127);
                    acc += joinf(g_s_hi, g_s_lo, ra) * joinf(g_vt_hi, g_vt_lo, rb + k);
                }
                vtout[((size_t)bh * LNc + lb * 128 + i) * VDc + nb * 128 + j] = acc;
            }
        }
    }
#endif
}

// ---------------- host ------------------------------------------------------
typedef CUresult (*EncodeFn)(CUtensorMap*, CUtensorMapDataType, cuuint32_t, void*,
                             const cuuint64_t*, const cuuint64_t*, const cuuint32_t*,
                             const cuuint32_t*, CUtensorMapInterleave, CUtensorMapSwizzle,
                             CUtensorMapL2promotion, CUtensorMapFloatOOBfill);

static void make_map(EncodeFn fn, CUtensorMap* m, void* base,
                     uint64_t d0, uint64_t d1, uint64_t strideB) {
    cuuint64_t dims[2]    = {d0, d1};
    cuuint64_t strides[1] = {strideB};
    cuuint32_t box[2]     = {64, 128};
    cuuint32_t es[2]      = {1, 1};
    fn(m, CU_TENSOR_MAP_DATA_TYPE_BFLOAT16, 2, base, dims, strides, box, es,
       CU_TENSOR_MAP_INTERLEAVE_NONE, CU_TENSOR_MAP_SWIZZLE_128B,
       CU_TENSOR_MAP_L2_PROMOTION_L2_128B, CU_TENSOR_MAP_FLOAT_OOB_FILL_NONE);
}

extern "C" void kernel_launch(void* const* d_in, const int* in_sizes, int n_in,
                              void* d_out, int out_size) {
    const float* X  = (const float*)d_in[0];
    const float* WQ = (const float*)d_in[1];
    const float* WK = (const float*)d_in[2];
    const float* WV = (const float*)d_in[3];

    float* out       = (float*)d_out;
    float* out_vt    = out;                           // [BH, L, VD]
    float* out_score = out + (size_t)BHc * LNc * VDc; // [BH, L, L]

    EncodeFn enc = nullptr;
    cudaDriverEntryPointQueryResult qr;
    cudaGetDriverEntryPoint("cuTensorMapEncodeTiled", (void**)&enc,
                            cudaEnableDefault, &qr);

    void *xh, *xl, *wh, *wl, *qh, *ql, *kh, *kl, *vh, *vl, *sh, *sl;
    cudaGetSymbolAddress(&xh, g_x_hi);  cudaGetSymbolAddress(&xl, g_x_lo);
    cudaGetSymbolAddress(&wh, g_w_hi);  cudaGetSymbolAddress(&wl, g_w_lo);
    cudaGetSymbolAddress(&qh, g_q_hi);  cudaGetSymbolAddress(&ql, g_q_lo);
    cudaGetSymbolAddress(&kh, g_k_hi);  cudaGetSymbolAddress(&kl, g_k_lo);
    cudaGetSymbolAddress(&vh, g_vt_hi); cudaGetSymbolAddress(&vl, g_vt_lo);
    cudaGetSymbolAddress(&sh, g_s_hi);  cudaGetSymbolAddress(&sl, g_s_lo);

    CUtensorMap mxh, mxl, mwh, mwl, mqh, mql, mkh, mkl, mvh, mvl, msh, msl;
    make_map(enc, &mxh, xh, 256, 32768, 512);
    make_map(enc, &mxl, xl, 256, 32768, 512);
    make_map(enc, &mwh, wh, 256, 1024, 512);
    make_map(enc, &mwl, wl, 256, 1024, 512);
    make_map(enc, &mqh, qh, 256, 32768, 512);
    make_map(enc, &mql, ql, 256, 32768, 512);
    make_map(enc, &mkh, kh, 256, 32768, 512);
    make_map(enc, &mkl, kl, 256, 32768, 512);
    make_map(enc, &mvh, vh, 2048, 8192, 4096);
    make_map(enc, &mvl, vl, 2048, 8192, 4096);
    make_map(enc, &msh, sh, 128, 294912, 256);
    make_map(enc, &msl, sl, 128, 294912, 256);

    cudaFuncSetAttribute(gemm_p<0>, cudaFuncAttributeMaxDynamicSharedMemorySize, SMEM_TOTAL);
    cudaFuncSetAttribute(gemm_p<1>, cudaFuncAttributeMaxDynamicSharedMemorySize, SMEM_TOTAL);
    cudaFuncSetAttribute(gemm_p<2>, cudaFuncAttributeMaxDynamicSharedMemorySize, SMEM_TOTAL);

    split_x_k<<<8192, 256>>>(X);
    split_w_k<<<1024, 256>>>(WQ, WK, WV);
    gemm_p<0><<<512,  256, SMEM_TOTAL>>>(mxh, mxl, mwh, mwl, nullptr, nullptr);
    gemm_p<1><<<1024, 256, SMEM_TOTAL>>>(mqh, mql, mkh, mkl, out_score, nullptr);
    gemm_p<2><<<512,  256, SMEM_TOTAL>>>(msh, msl, mvh, mvl, nullptr, out_vt);
}